// round 8
// baseline (speedup 1.0000x reference)
#include <cuda_runtime.h>
#include <cstddef>
#include <cstdint>

#define T_LEN 2048
#define BB 2
#define E_DIM 1024
#define H_NUM 16
#define D_HEAD 64
#define M_MEM 1024
#define NEGINF -1e9f

// ---------------- scratch (device globals; allocation-free) ----------------
__device__ float g_q [(size_t)BB * H_NUM * T_LEN * D_HEAD];
__device__ float g_k [(size_t)BB * H_NUM * T_LEN * D_HEAD];
__device__ float g_v [(size_t)BB * H_NUM * T_LEN * D_HEAD];
__device__ float g_km[(size_t)BB * H_NUM * M_MEM * D_HEAD];
__device__ float g_vm[(size_t)BB * H_NUM * M_MEM * D_HEAD];
__device__ float g_ctx[(size_t)T_LEN * BB * E_DIM];

// ---------------- tf32 helpers ---------------------------------------------
__device__ __forceinline__ float f2tf(float f) {
    uint32_t u;
    asm("cvt.rna.tf32.f32 %0, %1;" : "=r"(u) : "f"(f));
    return __uint_as_float(u);
}

__device__ __forceinline__ void mma_tf32(float* c, const uint32_t* a, const uint32_t* b) {
    asm volatile(
        "mma.sync.aligned.m16n8k8.row.col.f32.tf32.tf32.f32 "
        "{%0,%1,%2,%3}, {%4,%5,%6,%7}, {%8,%9}, {%0,%1,%2,%3};"
        : "+f"(c[0]), "+f"(c[1]), "+f"(c[2]), "+f"(c[3])
        : "r"(a[0]), "r"(a[1]), "r"(a[2]), "r"(a[3]), "r"(b[0]), "r"(b[1]));
}

// ldmatrix x4: 4 matrices of 8 rows x 16B.  Lane l supplies the row pointer
// for matrix (l>>3), row (l&7).  Result reg m of lane l = word[l>>2][l&3]
// of matrix m.  With tf32 data (1 word = 1 element) this is exactly the
// m16n8k8 fragment layout.
__device__ __forceinline__ void ldsm4(uint32_t* r, const float* p) {
    uint32_t a = (uint32_t)__cvta_generic_to_shared(p);
    asm volatile("ldmatrix.sync.aligned.m8n8.x4.shared.b16 {%0,%1,%2,%3}, [%4];"
                 : "=r"(r[0]), "=r"(r[1]), "=r"(r[2]), "=r"(r[3]) : "r"(a));
}

// ---------------- tf32 GEMM, 2-stage pipelined, LDSM operands -------------
// A: [Mrows,1024] row-major. W: [1024,1024] row-major (out-feature major).
// MODE 0: out[r*1024+c];  MODE 1: scatter to [B,H,L,D].
#define GEMM_STG (128 * 36)
template <int MODE>
__global__ void __launch_bounds__(256)
gemm_tc(const float* __restrict__ A, const float* __restrict__ W,
        const float* __restrict__ bias, float* __restrict__ out,
        float scale, int Lrows)
{
    extern __shared__ float gsm[];
    float* Asb = gsm;
    float* Bsb = gsm + 2 * GEMM_STG;

    const int tid  = threadIdx.x;
    const int warp = tid >> 5;
    const int lane = tid & 31;
    const int g = lane >> 2, t = lane & 3;
    const int wm = warp >> 2;
    const int wn = warp & 3;
    const int row0 = blockIdx.y * 128;
    const int col0 = blockIdx.x * 128;

    const int lr = tid >> 1;
    const int lc = (tid & 1) * 16;

    // per-lane LDSM row-pointer offsets (in floats, within a stage)
    const int aoff = (wm * 64 + (lane & 7) + ((lane >> 3) & 1) * 8) * 36 + (lane >> 4) * 4;
    const int boff = (wn * 32 + (lane & 7)) * 36 + (lane >> 3) * 4;

    float acc[4][4][4];
#pragma unroll
    for (int mt = 0; mt < 4; mt++)
#pragma unroll
        for (int nt = 0; nt < 4; nt++)
#pragma unroll
            for (int i = 0; i < 4; i++) acc[mt][nt][i] = 0.f;

    const float* Ap = A + (size_t)(row0 + lr) * E_DIM + lc;
    const float* Wp = W + (size_t)(col0 + lr) * E_DIM + lc;

    float4 av[4], wv[4];
#pragma unroll
    for (int i = 0; i < 4; i++) { av[i] = *(const float4*)(Ap + i * 4);
                                  wv[i] = *(const float4*)(Wp + i * 4); }
    {
        float* As = Asb; float* Bs = Bsb;
#pragma unroll
        for (int i = 0; i < 4; i++) {
            As[lr * 36 + lc + i*4 + 0] = f2tf(av[i].x);
            As[lr * 36 + lc + i*4 + 1] = f2tf(av[i].y);
            As[lr * 36 + lc + i*4 + 2] = f2tf(av[i].z);
            As[lr * 36 + lc + i*4 + 3] = f2tf(av[i].w);
            Bs[lr * 36 + lc + i*4 + 0] = f2tf(wv[i].x);
            Bs[lr * 36 + lc + i*4 + 1] = f2tf(wv[i].y);
            Bs[lr * 36 + lc + i*4 + 2] = f2tf(wv[i].z);
            Bs[lr * 36 + lc + i*4 + 3] = f2tf(wv[i].w);
        }
    }
    __syncthreads();

    for (int kt = 0; kt < E_DIM; kt += 32) {
        const int cur = (kt >> 5) & 1;
        const int nxt = cur ^ 1;
        const bool more = (kt + 32) < E_DIM;
        if (more) {
#pragma unroll
            for (int i = 0; i < 4; i++) {
                av[i] = *(const float4*)(Ap + kt + 32 + i * 4);
                wv[i] = *(const float4*)(Wp + kt + 32 + i * 4);
            }
        }

        const float* As = Asb + cur * GEMM_STG;
        const float* Bs = Bsb + cur * GEMM_STG;
#pragma unroll
        for (int kp = 0; kp < 2; kp++) {          // covers k 16kp .. 16kp+15
            uint32_t af[4][8];
#pragma unroll
            for (int mt = 0; mt < 4; mt++) {
                ldsm4(af[mt] + 0, As + aoff + mt * 16 * 36 + 16 * kp);
                ldsm4(af[mt] + 4, As + aoff + mt * 16 * 36 + 16 * kp + 8);
            }
#pragma unroll
            for (int nt = 0; nt < 4; nt++) {
                uint32_t bf[4];
                ldsm4(bf, Bs + boff + nt * 8 * 36 + 16 * kp);
#pragma unroll
                for (int mt = 0; mt < 4; mt++) {
                    mma_tf32(acc[mt][nt], af[mt] + 0, bf + 0);
                    mma_tf32(acc[mt][nt], af[mt] + 4, bf + 2);
                }
            }
        }

        if (more) {
            float* Asn = Asb + nxt * GEMM_STG;
            float* Bsn = Bsb + nxt * GEMM_STG;
#pragma unroll
            for (int i = 0; i < 4; i++) {
                Asn[lr * 36 + lc + i*4 + 0] = f2tf(av[i].x);
                Asn[lr * 36 + lc + i*4 + 1] = f2tf(av[i].y);
                Asn[lr * 36 + lc + i*4 + 2] = f2tf(av[i].z);
                Asn[lr * 36 + lc + i*4 + 3] = f2tf(av[i].w);
                Bsn[lr * 36 + lc + i*4 + 0] = f2tf(wv[i].x);
                Bsn[lr * 36 + lc + i*4 + 1] = f2tf(wv[i].y);
                Bsn[lr * 36 + lc + i*4 + 2] = f2tf(wv[i].z);
                Bsn[lr * 36 + lc + i*4 + 3] = f2tf(wv[i].w);
            }
        }
        __syncthreads();
    }

#pragma unroll
    for (int mt = 0; mt < 4; mt++) {
#pragma unroll
        for (int nt = 0; nt < 4; nt++) {
#pragma unroll
            for (int i = 0; i < 2; i++) {
#pragma unroll
                for (int j = 0; j < 2; j++) {
                    const int r = row0 + wm * 64 + mt * 16 + g + i * 8;
                    const int c = col0 + wn * 32 + nt * 8 + 2 * t + j;
                    const float val = (acc[mt][nt][i * 2 + j] + bias[c]) * scale;
                    if (MODE == 0) {
                        out[(size_t)r * E_DIM + c] = val;
                    } else {
                        const int tt = r / BB, b = r % BB;
                        const int h = c >> 6, d = c & 63;
                        out[(((size_t)b * H_NUM + h) * Lrows + tt) * D_HEAD + d] = val;
                    }
                }
            }
        }
    }
}

// ---------------- attention: FA2-style, LDSM + double-buffered K/V --------
// CTA: 128 queries, 8 warps; warp w owns rows [16w, 16w+16). Key tile = 64.
// Smem: 2 stages x (Ks[64][68] + Vt[64][68]) + per-warp P buffers.
#define ATT_STG (2 * 64 * 68)      // floats per stage (K + V)
template <bool LOCAL>
__global__ void __launch_bounds__(256, 1)
attn_fa(const float* __restrict__ Qg, const float* __restrict__ Kg,
        const float* __restrict__ Vg, const float* __restrict__ pos,
        const float* __restrict__ memb, float* __restrict__ ctx, int Skeys)
{
    extern __shared__ float sm[];
    float* Ps = sm + 2 * ATT_STG;   // 8 x [16][68]

    const int tid  = threadIdx.x;
    const int warp = tid >> 5;
    const int lane = tid & 31;
    const int g = lane >> 2, t = lane & 3;
    const int h  = blockIdx.y;
    const int b  = blockIdx.z;
    const int t0 = blockIdx.x * 128;
    const int qrow = t0 + warp * 16;
    const size_t qbase  = (((size_t)b * H_NUM + h) * T_LEN + qrow) * D_HEAD;
    const size_t kvbase = ((size_t)b * H_NUM + h) * (size_t)Skeys * D_HEAD;
    float* Pw = Ps + warp * 16 * 68;

    // per-lane LDSM row-pointer offsets (floats)
    const int kvoff = (lane & 7) * 68 + (lane >> 3) * 4;                       // B-frags (K, V)
    const int poff  = ((lane & 7) + ((lane >> 3) & 1) * 8) * 68 + (lane >> 4) * 4; // A-frags (P)

    // loader indices: each thread handles 4 rows' float4 chunks
    const int ldr = tid >> 4;           // 0..15 -> rows ldr, ldr+16, ...
    const int ldc = (tid & 15) * 4;     // col

    // Q fragments in registers (loaded once)
    uint32_t qf[8][4];
#pragma unroll
    for (int kk8 = 0; kk8 < 8; kk8++) {
        const int k = kk8 * 8;
        qf[kk8][0] = __float_as_uint(f2tf(__ldg(Qg + qbase + (size_t)g       * 64 + k + t    )));
        qf[kk8][1] = __float_as_uint(f2tf(__ldg(Qg + qbase + (size_t)(g + 8) * 64 + k + t    )));
        qf[kk8][2] = __float_as_uint(f2tf(__ldg(Qg + qbase + (size_t)g       * 64 + k + t + 4)));
        qf[kk8][3] = __float_as_uint(f2tf(__ldg(Qg + qbase + (size_t)(g + 8) * 64 + k + t + 4)));
    }

    float m0 = -1e30f, m1 = -1e30f;
    float l0 = 0.f, l1 = 0.f;
    float O[8][4];
#pragma unroll
    for (int nt = 0; nt < 8; nt++)
#pragma unroll
        for (int i = 0; i < 4; i++) O[nt][i] = 0.f;

    const int send = LOCAL ? (t0 + 128) : Skeys;

    // prologue: load tile 0 into regs, stage 0
    float4 ka[4], va[4];
#pragma unroll
    for (int i = 0; i < 4; i++) {
        const int r = ldr + i * 16;
        ka[i] = *(const float4*)(Kg + kvbase + (size_t)r * 64 + ldc);
        va[i] = *(const float4*)(Vg + kvbase + (size_t)r * 64 + ldc);
    }
    {
        float* Ks = sm;
        float* Vt = sm + 64 * 68;
#pragma unroll
        for (int i = 0; i < 4; i++) {
            const int r = ldr + i * 16;
            *(float4*)(Ks + r * 68 + ldc) =
                make_float4(f2tf(ka[i].x), f2tf(ka[i].y), f2tf(ka[i].z), f2tf(ka[i].w));
            Vt[(ldc + 0) * 68 + r] = f2tf(va[i].x);
            Vt[(ldc + 1) * 68 + r] = f2tf(va[i].y);
            Vt[(ldc + 2) * 68 + r] = f2tf(va[i].z);
            Vt[(ldc + 3) * 68 + r] = f2tf(va[i].w);
        }
    }
    __syncthreads();

    for (int s0 = 0, idx = 0; s0 < send; s0 += 64, idx++) {
        const int cur = idx & 1;
        const bool more = (s0 + 64) < send;
        if (more) {
#pragma unroll
            for (int i = 0; i < 4; i++) {
                const int r = ldr + i * 16;
                ka[i] = *(const float4*)(Kg + kvbase + (size_t)(s0 + 64 + r) * 64 + ldc);
                va[i] = *(const float4*)(Vg + kvbase + (size_t)(s0 + 64 + r) * 64 + ldc);
            }
        }

        const float* Ks = sm + cur * ATT_STG;
        const float* Vt = Ks + 64 * 68;

        // ---- S = Q K^T ----
        float Sa[8][4];
#pragma unroll
        for (int nt = 0; nt < 8; nt++)
#pragma unroll
            for (int i = 0; i < 4; i++) Sa[nt][i] = 0.f;
#pragma unroll
        for (int kp = 0; kp < 4; kp++) {          // k-steps 2kp, 2kp+1
#pragma unroll
            for (int nt = 0; nt < 8; nt++) {
                uint32_t bf[4];
                ldsm4(bf, Ks + kvoff + nt * 8 * 68 + 16 * kp);
                mma_tf32(Sa[nt], qf[2 * kp],     bf + 0);
                mma_tf32(Sa[nt], qf[2 * kp + 1], bf + 2);
            }
        }

        // ---- position encoding + causal mask ----
        if (LOCAL) {
            const int r0 = qrow + g, r1 = qrow + g + 8;
            const size_t pb0 = ((size_t)h * T_LEN + r0) * (size_t)T_LEN + s0;
            const size_t pb1 = ((size_t)h * T_LEN + r1) * (size_t)T_LEN + s0;
#pragma unroll
            for (int nt = 0; nt < 8; nt++) {
                const int c = nt * 8 + 2 * t;
                const float2 p0 = *(const float2*)(pos + pb0 + c);
                const float2 p1 = *(const float2*)(pos + pb1 + c);
                Sa[nt][0] += p0.x; Sa[nt][1] += p0.y;
                Sa[nt][2] += p1.x; Sa[nt][3] += p1.y;
            }
            if (s0 + 63 > qrow) {                  // only diagonal tiles mask
#pragma unroll
                for (int nt = 0; nt < 8; nt++) {
                    const int gc = s0 + nt * 8 + 2 * t;
                    if (gc     > r0) Sa[nt][0] = NEGINF;
                    if (gc + 1 > r0) Sa[nt][1] = NEGINF;
                    if (gc     > r1) Sa[nt][2] = NEGINF;
                    if (gc + 1 > r1) Sa[nt][3] = NEGINF;
                }
            }
        }

        // ---- online softmax in registers ----
        float mn0 = m0, mn1 = m1;
#pragma unroll
        for (int nt = 0; nt < 8; nt++) {
            mn0 = fmaxf(mn0, fmaxf(Sa[nt][0], Sa[nt][1]));
            mn1 = fmaxf(mn1, fmaxf(Sa[nt][2], Sa[nt][3]));
        }
        mn0 = fmaxf(mn0, __shfl_xor_sync(0xffffffffu, mn0, 1));
        mn0 = fmaxf(mn0, __shfl_xor_sync(0xffffffffu, mn0, 2));
        mn1 = fmaxf(mn1, __shfl_xor_sync(0xffffffffu, mn1, 1));
        mn1 = fmaxf(mn1, __shfl_xor_sync(0xffffffffu, mn1, 2));
        const float sc0 = __expf(m0 - mn0);
        const float sc1 = __expf(m1 - mn1);
        m0 = mn0; m1 = mn1;
        float sum0 = 0.f, sum1 = 0.f;
#pragma unroll
        for (int nt = 0; nt < 8; nt++) {
            float p0 = __expf(Sa[nt][0] - m0);
            float p1 = __expf(Sa[nt][1] - m0);
            float p2 = __expf(Sa[nt][2] - m1);
            float p3 = __expf(Sa[nt][3] - m1);
            sum0 += p0 + p1; sum1 += p2 + p3;
            Sa[nt][0] = f2tf(p0); Sa[nt][1] = f2tf(p1);
            Sa[nt][2] = f2tf(p2); Sa[nt][3] = f2tf(p3);
        }
        l0 = l0 * sc0 + sum0;
        l1 = l1 * sc1 + sum1;

#pragma unroll
        for (int nt = 0; nt < 8; nt++) {
            O[nt][0] *= sc0; O[nt][1] *= sc0;
            O[nt][2] *= sc1; O[nt][3] *= sc1;
        }

        // ---- P to warp-private smem, reload as A-frags via LDSM ----
        __syncwarp();
#pragma unroll
        for (int nt = 0; nt < 8; nt++) {
            const int c = nt * 8 + 2 * t;
            *(float2*)(Pw + g       * 68 + c) = make_float2(Sa[nt][0], Sa[nt][1]);
            *(float2*)(Pw + (g + 8) * 68 + c) = make_float2(Sa[nt][2], Sa[nt][3]);
        }
        __syncwarp();

        // ---- O += P V ----
#pragma unroll
        for (int kp = 0; kp < 4; kp++) {
            uint32_t a0[4], a1[4];
            ldsm4(a0, Pw + poff + 16 * kp);
            ldsm4(a1, Pw + poff + 16 * kp + 8);
#pragma unroll
            for (int nt = 0; nt < 8; nt++) {
                uint32_t bf[4];
                ldsm4(bf, Vt + kvoff + nt * 8 * 68 + 16 * kp);
                mma_tf32(O[nt], a0, bf + 0);
                mma_tf32(O[nt], a1, bf + 2);
            }
        }

        // ---- stage next tile ----
        if (more) {
            float* Ksn = sm + (cur ^ 1) * ATT_STG;
            float* Vtn = Ksn + 64 * 68;
#pragma unroll
            for (int i = 0; i < 4; i++) {
                const int r = ldr + i * 16;
                *(float4*)(Ksn + r * 68 + ldc) =
                    make_float4(f2tf(ka[i].x), f2tf(ka[i].y), f2tf(ka[i].z), f2tf(ka[i].w));
                Vtn[(ldc + 0) * 68 + r] = f2tf(va[i].x);
                Vtn[(ldc + 1) * 68 + r] = f2tf(va[i].y);
                Vtn[(ldc + 2) * 68 + r] = f2tf(va[i].z);
                Vtn[(ldc + 3) * 68 + r] = f2tf(va[i].w);
            }
        }
        __syncthreads();
    }

    // ---- epilogue ----
    l0 += __shfl_xor_sync(0xffffffffu, l0, 1);
    l0 += __shfl_xor_sync(0xffffffffu, l0, 2);
    l1 += __shfl_xor_sync(0xffffffffu, l1, 1);
    l1 += __shfl_xor_sync(0xffffffffu, l1, 2);

    const float gate = 1.f / (1.f + __expf(-memb[h]));
    const float wgt  = LOCAL ? (1.f - gate) : gate;
    const float li0 = wgt / l0;
    const float li1 = wgt / l1;

    const int r0 = qrow + g, r1 = qrow + g + 8;
#pragma unroll
    for (int nt = 0; nt < 8; nt++) {
        const int c = h * 64 + nt * 8 + 2 * t;
        const size_t i0 = ((size_t)r0 * BB + b) * E_DIM + c;
        const size_t i1 = ((size_t)r1 * BB + b) * E_DIM + c;
        if (LOCAL) {
            *(float2*)(ctx + i0) = make_float2(O[nt][0] * li0, O[nt][1] * li0);
            *(float2*)(ctx + i1) = make_float2(O[nt][2] * li1, O[nt][3] * li1);
        } else {
            ctx[i0]     += O[nt][0] * li0;
            ctx[i0 + 1] += O[nt][1] * li0;
            ctx[i1]     += O[nt][2] * li1;
            ctx[i1 + 1] += O[nt][3] * li1;
        }
    }
}

// ---------------- launch ---------------------------------------------------
extern "C" void kernel_launch(void* const* d_in, const int* in_sizes, int n_in,
                              void* d_out, int out_size)
{
    const float* query = (const float*)d_in[0];
    const float* pos   = (const float*)d_in[1];
    const float* lcr   = (const float*)d_in[2];
    const float* q_w   = (const float*)d_in[3];
    const float* q_b   = (const float*)d_in[4];
    const float* k_w   = (const float*)d_in[5];
    const float* k_b   = (const float*)d_in[6];
    const float* v_w   = (const float*)d_in[7];
    const float* v_b   = (const float*)d_in[8];
    const float* out_w = (const float*)d_in[9];
    const float* out_b = (const float*)d_in[10];
    const float* memb  = (const float*)d_in[11];
    float* out = (float*)d_out;

    float *qp, *kp, *vp, *kmp, *vmp, *ctxp;
    cudaGetSymbolAddress((void**)&qp,   g_q);
    cudaGetSymbolAddress((void**)&kp,   g_k);
    cudaGetSymbolAddress((void**)&vp,   g_v);
    cudaGetSymbolAddress((void**)&kmp,  g_km);
    cudaGetSymbolAddress((void**)&vmp,  g_vm);
    cudaGetSymbolAddress((void**)&ctxp, g_ctx);

    const dim3 tpb(256);
    const float qscale = 0.125f;  // D^-0.5

    const int gsmem = 4 * GEMM_STG * (int)sizeof(float);  // 73728 B
    cudaFuncSetAttribute(gemm_tc<0>, cudaFuncAttributeMaxDynamicSharedMemorySize, gsmem);
    cudaFuncSetAttribute(gemm_tc<1>, cudaFuncAttributeMaxDynamicSharedMemorySize, gsmem);

    // projections
    const dim3 gq(E_DIM / 128, (T_LEN * BB) / 128);
    gemm_tc<1><<<gq, tpb, gsmem>>>(query, q_w, q_b, qp, qscale, T_LEN);
    gemm_tc<1><<<gq, tpb, gsmem>>>(query, k_w, k_b, kp, 1.f, T_LEN);
    gemm_tc<1><<<gq, tpb, gsmem>>>(query, v_w, v_b, vp, 1.f, T_LEN);
    const dim3 gm(E_DIM / 128, (M_MEM * BB) / 128);
    gemm_tc<1><<<gm, tpb, gsmem>>>(lcr,                              k_w, k_b, kmp, 1.f, M_MEM);
    gemm_tc<1><<<gm, tpb, gsmem>>>(lcr + (size_t)M_MEM * BB * E_DIM, v_w, v_b, vmp, 1.f, M_MEM);

    // attention
    const int asmem = (2 * ATT_STG + 8 * 16 * 68) * (int)sizeof(float);  // 104448 B
    cudaFuncSetAttribute(attn_fa<true>,  cudaFuncAttributeMaxDynamicSharedMemorySize, asmem);
    cudaFuncSetAttribute(attn_fa<false>, cudaFuncAttributeMaxDynamicSharedMemorySize, asmem);
    const dim3 ga(T_LEN / 128, H_NUM, BB);
    attn_fa<true ><<<ga, tpb, asmem>>>(qp, kp,  vp,  pos, memb, ctxp, T_LEN);
    attn_fa<false><<<ga, tpb, asmem>>>(qp, kmp, vmp, pos, memb, ctxp, M_MEM);

    // output projection
    const dim3 go(E_DIM / 128, (T_LEN * BB) / 128);
    gemm_tc<0><<<go, tpb, gsmem>>>(ctxp, out_w, out_b, out, 1.f, T_LEN);
}

// round 9
// speedup vs baseline: 1.7304x; 1.7304x over previous
#include <cuda_runtime.h>
#include <cstddef>
#include <cstdint>

#define T_LEN 2048
#define BB 2
#define E_DIM 1024
#define H_NUM 16
#define D_HEAD 64
#define M_MEM 1024
#define NEGINF -1e9f

// ---------------- scratch (device globals; allocation-free) ----------------
__device__ float g_q  [(size_t)BB * H_NUM * T_LEN * D_HEAD];
__device__ float g_k  [(size_t)BB * H_NUM * T_LEN * D_HEAD];
__device__ float g_v  [(size_t)BB * H_NUM * T_LEN * D_HEAD];
__device__ float g_km [(size_t)BB * H_NUM * M_MEM * D_HEAD];
__device__ float g_vm [(size_t)BB * H_NUM * M_MEM * D_HEAD];
__device__ float g_c1 [(size_t)T_LEN * BB * E_DIM];
__device__ float g_c2 [(size_t)T_LEN * BB * E_DIM];

// ---------------- tf32 helpers ---------------------------------------------
__device__ __forceinline__ float f2tf(float f) {
    uint32_t u;
    asm("cvt.rna.tf32.f32 %0, %1;" : "=r"(u) : "f"(f));
    return __uint_as_float(u);
}

__device__ __forceinline__ void mma_tf32(float* c, const uint32_t* a, const uint32_t* b) {
    asm volatile(
        "mma.sync.aligned.m16n8k8.row.col.f32.tf32.tf32.f32 "
        "{%0,%1,%2,%3}, {%4,%5,%6,%7}, {%8,%9}, {%0,%1,%2,%3};"
        : "+f"(c[0]), "+f"(c[1]), "+f"(c[2]), "+f"(c[3])
        : "r"(a[0]), "r"(a[1]), "r"(a[2]), "r"(a[3]), "r"(b[0]), "r"(b[1]));
}

// ---------------- merged projection GEMM (5 configs, one launch) -----------
// y[r,c] = (sum_e A[r,e]*W[c,e] + bias[c]) * scale, scattered to [B,H,L,D].
struct GC {
    const float* A; const float* W; const float* bias; float* out;
    float scale; int ny; int Lrows;
};

#define GEMM_STG (128 * 36)

__device__ __forceinline__ void gemm_body(
    const float* __restrict__ A, const float* __restrict__ A2,
    const float* __restrict__ W, const float* __restrict__ bias,
    float* __restrict__ out, float scale, int Lrows, int scatter,
    float* gsm)
{
    float* Asb = gsm;
    float* Bsb = gsm + 2 * GEMM_STG;

    const int tid  = threadIdx.x;
    const int warp = tid >> 5;
    const int lane = tid & 31;
    const int g = lane >> 2, t = lane & 3;
    const int wm = warp >> 2;
    const int wn = warp & 3;
    const int row0 = blockIdx.y * 128;
    const int col0 = blockIdx.x * 128;

    const int lr = tid >> 1;
    const int lc = (tid & 1) * 16;

    float acc[4][4][4];
#pragma unroll
    for (int mt = 0; mt < 4; mt++)
#pragma unroll
        for (int nt = 0; nt < 4; nt++)
#pragma unroll
            for (int i = 0; i < 4; i++) acc[mt][nt][i] = 0.f;

    const float* Ap  = A + (size_t)(row0 + lr) * E_DIM + lc;
    const float* A2p = A2 ? A2 + (size_t)(row0 + lr) * E_DIM + lc : nullptr;
    const float* Wp  = W + (size_t)(col0 + lr) * E_DIM + lc;

    float4 av[4], wv[4];
#pragma unroll
    for (int i = 0; i < 4; i++) {
        av[i] = *(const float4*)(Ap + i * 4);
        wv[i] = *(const float4*)(Wp + i * 4);
        if (A2p) {
            const float4 a2 = *(const float4*)(A2p + i * 4);
            av[i].x += a2.x; av[i].y += a2.y; av[i].z += a2.z; av[i].w += a2.w;
        }
    }
    {
        float* As = Asb; float* Bs = Bsb;
#pragma unroll
        for (int i = 0; i < 4; i++) {
            As[lr * 36 + lc + i*4 + 0] = f2tf(av[i].x);
            As[lr * 36 + lc + i*4 + 1] = f2tf(av[i].y);
            As[lr * 36 + lc + i*4 + 2] = f2tf(av[i].z);
            As[lr * 36 + lc + i*4 + 3] = f2tf(av[i].w);
            Bs[lr * 36 + lc + i*4 + 0] = f2tf(wv[i].x);
            Bs[lr * 36 + lc + i*4 + 1] = f2tf(wv[i].y);
            Bs[lr * 36 + lc + i*4 + 2] = f2tf(wv[i].z);
            Bs[lr * 36 + lc + i*4 + 3] = f2tf(wv[i].w);
        }
    }
    __syncthreads();

    for (int kt = 0; kt < E_DIM; kt += 32) {
        const int cur = (kt >> 5) & 1;
        const int nxt = cur ^ 1;
        const bool more = (kt + 32) < E_DIM;
        if (more) {
#pragma unroll
            for (int i = 0; i < 4; i++) {
                av[i] = *(const float4*)(Ap + kt + 32 + i * 4);
                wv[i] = *(const float4*)(Wp + kt + 32 + i * 4);
                if (A2p) {
                    const float4 a2 = *(const float4*)(A2p + kt + 32 + i * 4);
                    av[i].x += a2.x; av[i].y += a2.y; av[i].z += a2.z; av[i].w += a2.w;
                }
            }
        }

        const float* As = Asb + cur * GEMM_STG;
        const float* Bs = Bsb + cur * GEMM_STG;
#pragma unroll
        for (int kk = 0; kk < 32; kk += 8) {
            uint32_t af[4][4], bf[4][2];
#pragma unroll
            for (int mt = 0; mt < 4; mt++) {
                const int m = wm * 64 + mt * 16;
                af[mt][0] = __float_as_uint(As[(m + g    ) * 36 + kk + t    ]);
                af[mt][1] = __float_as_uint(As[(m + g + 8) * 36 + kk + t    ]);
                af[mt][2] = __float_as_uint(As[(m + g    ) * 36 + kk + t + 4]);
                af[mt][3] = __float_as_uint(As[(m + g + 8) * 36 + kk + t + 4]);
            }
#pragma unroll
            for (int nt = 0; nt < 4; nt++) {
                const int n = wn * 32 + nt * 8;
                bf[nt][0] = __float_as_uint(Bs[(n + g) * 36 + kk + t    ]);
                bf[nt][1] = __float_as_uint(Bs[(n + g) * 36 + kk + t + 4]);
            }
#pragma unroll
            for (int mt = 0; mt < 4; mt++)
#pragma unroll
                for (int nt = 0; nt < 4; nt++)
                    mma_tf32(acc[mt][nt], af[mt], bf[nt]);
        }

        if (more) {
            float* Asn = Asb + nxt * GEMM_STG;
            float* Bsn = Bsb + nxt * GEMM_STG;
#pragma unroll
            for (int i = 0; i < 4; i++) {
                Asn[lr * 36 + lc + i*4 + 0] = f2tf(av[i].x);
                Asn[lr * 36 + lc + i*4 + 1] = f2tf(av[i].y);
                Asn[lr * 36 + lc + i*4 + 2] = f2tf(av[i].z);
                Asn[lr * 36 + lc + i*4 + 3] = f2tf(av[i].w);
                Bsn[lr * 36 + lc + i*4 + 0] = f2tf(wv[i].x);
                Bsn[lr * 36 + lc + i*4 + 1] = f2tf(wv[i].y);
                Bsn[lr * 36 + lc + i*4 + 2] = f2tf(wv[i].z);
                Bsn[lr * 36 + lc + i*4 + 3] = f2tf(wv[i].w);
            }
        }
        __syncthreads();
    }

#pragma unroll
    for (int mt = 0; mt < 4; mt++) {
#pragma unroll
        for (int nt = 0; nt < 4; nt++) {
#pragma unroll
            for (int i = 0; i < 2; i++) {
#pragma unroll
                for (int j = 0; j < 2; j++) {
                    const int r = row0 + wm * 64 + mt * 16 + g + i * 8;
                    const int c = col0 + wn * 32 + nt * 8 + 2 * t + j;
                    const float val = (acc[mt][nt][i * 2 + j] + bias[c]) * scale;
                    if (scatter) {
                        const int tt = r / BB, b = r % BB;
                        const int h = c >> 6, d = c & 63;
                        out[(((size_t)b * H_NUM + h) * Lrows + tt) * D_HEAD + d] = val;
                    } else {
                        out[(size_t)r * E_DIM + c] = val;
                    }
                }
            }
        }
    }
}

__global__ void __launch_bounds__(256)
gemm_proj(GC c0, GC c1, GC c2, GC c3, GC c4)
{
    extern __shared__ float gsm[];
    const int z = blockIdx.z;
    GC c = c0;
    if (z == 1) c = c1; else if (z == 2) c = c2;
    else if (z == 3) c = c3; else if (z == 4) c = c4;
    if ((int)blockIdx.y >= c.ny) return;
    gemm_body(c.A, nullptr, c.W, c.bias, c.out, c.scale, c.Lrows, 1, gsm);
}

__global__ void __launch_bounds__(256)
gemm_out_k(const float* __restrict__ A, const float* __restrict__ A2,
           const float* __restrict__ W, const float* __restrict__ bias,
           float* __restrict__ out)
{
    extern __shared__ float gsm[];
    gemm_body(A, A2, W, bias, out, 1.f, T_LEN, 0, gsm);
}

// ---------------- fused attention (local + memory in one launch) -----------
// grid: (16, H, 4); z = kind*2 + b.  kind 0: local (causal + pos) -> ctx1,
// kind 1: memory -> ctx2.  CTA: 128 q rows, 8 warps (16 rows each), 64-key
// tiles.  Single smem stage; next K/V tile prefetched into registers.
// Vt uses addr = d*68 + (d>>3)*4 + s  (conflict-free reads, 2-way stores).
#define VT(d, s) ((d) * 68 + ((d) >> 3) * 4 + (s))

__global__ void __launch_bounds__(256, 1)
attn_fused(const float* __restrict__ Qg,
           const float* __restrict__ Kl, const float* __restrict__ Vl,
           const float* __restrict__ Km, const float* __restrict__ Vm,
           const float* __restrict__ pos, const float* __restrict__ memb,
           float* __restrict__ ctx1, float* __restrict__ ctx2)
{
    extern __shared__ float sm[];
    float* Ks = sm;                       // [64][68] (s, d)
    float* Vt = Ks + 64 * 68;             // VT layout, 64*68+32 floats
    float* Ps = Vt + 64 * 68 + 32;        // 8 x [16][68]

    const int z    = blockIdx.z;
    const int kind = z >> 1;
    const int b    = z & 1;
    const bool LOCAL = (kind == 0);
    const float* Kg = LOCAL ? Kl : Km;
    const float* Vg = LOCAL ? Vl : Vm;
    const int Skeys = LOCAL ? T_LEN : M_MEM;
    float* ctx = LOCAL ? ctx1 : ctx2;

    const int tid  = threadIdx.x;
    const int warp = tid >> 5;
    const int lane = tid & 31;
    const int g = lane >> 2, t = lane & 3;
    const int h  = blockIdx.y;
    const int t0 = blockIdx.x * 128;
    const int qrow = t0 + warp * 16;
    const size_t qbase  = (((size_t)b * H_NUM + h) * T_LEN + qrow) * D_HEAD;
    const size_t kvbase = ((size_t)b * H_NUM + h) * (size_t)Skeys * D_HEAD;
    float* Pw = Ps + warp * 16 * 68;

    const int ldr = tid >> 4;           // rows ldr, ldr+16, ldr+32, ldr+48
    const int ldc = (tid & 15) * 4;

    // Q fragments in registers (loaded once)
    uint32_t qf[8][4];
#pragma unroll
    for (int kk8 = 0; kk8 < 8; kk8++) {
        const int k = kk8 * 8;
        qf[kk8][0] = __float_as_uint(f2tf(__ldg(Qg + qbase + (size_t)g       * 64 + k + t    )));
        qf[kk8][1] = __float_as_uint(f2tf(__ldg(Qg + qbase + (size_t)(g + 8) * 64 + k + t    )));
        qf[kk8][2] = __float_as_uint(f2tf(__ldg(Qg + qbase + (size_t)g       * 64 + k + t + 4)));
        qf[kk8][3] = __float_as_uint(f2tf(__ldg(Qg + qbase + (size_t)(g + 8) * 64 + k + t + 4)));
    }

    float m0 = -1e30f, m1 = -1e30f;
    float l0 = 0.f, l1 = 0.f;
    float O[8][4];
#pragma unroll
    for (int nt = 0; nt < 8; nt++)
#pragma unroll
        for (int i = 0; i < 4; i++) O[nt][i] = 0.f;

    const int send = LOCAL ? (t0 + 128) : Skeys;

    // prologue: prefetch tile 0 into registers
    float4 ka[4], va[4];
#pragma unroll
    for (int i = 0; i < 4; i++) {
        const int r = ldr + i * 16;
        ka[i] = *(const float4*)(Kg + kvbase + (size_t)r * 64 + ldc);
        va[i] = *(const float4*)(Vg + kvbase + (size_t)r * 64 + ldc);
    }

    for (int s0 = 0; s0 < send; s0 += 64) {
        const bool more = (s0 + 64) < send;

        __syncthreads();   // previous tile's smem reads complete
        // stage current tile from registers
#pragma unroll
        for (int i = 0; i < 4; i++) {
            const int r = ldr + i * 16;
            *(float4*)(Ks + r * 68 + ldc) =
                make_float4(f2tf(ka[i].x), f2tf(ka[i].y), f2tf(ka[i].z), f2tf(ka[i].w));
            Vt[VT(ldc + 0, r)] = f2tf(va[i].x);
            Vt[VT(ldc + 1, r)] = f2tf(va[i].y);
            Vt[VT(ldc + 2, r)] = f2tf(va[i].z);
            Vt[VT(ldc + 3, r)] = f2tf(va[i].w);
        }
        __syncthreads();

        // prefetch next tile (overlaps all compute below)
        if (more) {
#pragma unroll
            for (int i = 0; i < 4; i++) {
                const int r = ldr + i * 16;
                ka[i] = *(const float4*)(Kg + kvbase + (size_t)(s0 + 64 + r) * 64 + ldc);
                va[i] = *(const float4*)(Vg + kvbase + (size_t)(s0 + 64 + r) * 64 + ldc);
            }
        }

        // fully-masked tile for this warp? (exact skip)
        if (LOCAL && s0 > qrow + 15) continue;

        // prefetch position encoding (consumed after the S MMAs)
        float2 pr0[8], pr1[8];
        if (LOCAL) {
            const size_t pb0 = ((size_t)h * T_LEN + qrow + g    ) * (size_t)T_LEN + s0;
            const size_t pb1 = ((size_t)h * T_LEN + qrow + g + 8) * (size_t)T_LEN + s0;
#pragma unroll
            for (int nt = 0; nt < 8; nt++) {
                pr0[nt] = *(const float2*)(pos + pb0 + nt * 8 + 2 * t);
                pr1[nt] = *(const float2*)(pos + pb1 + nt * 8 + 2 * t);
            }
        }

        // ---- S = Q K^T ----
        float Sa[8][4];
#pragma unroll
        for (int nt = 0; nt < 8; nt++)
#pragma unroll
            for (int i = 0; i < 4; i++) Sa[nt][i] = 0.f;
#pragma unroll
        for (int kk8 = 0; kk8 < 8; kk8++) {
            const int kk = kk8 * 8;
#pragma unroll
            for (int nt = 0; nt < 8; nt++) {
                uint32_t bf[2];
                bf[0] = __float_as_uint(Ks[(nt * 8 + g) * 68 + kk + t    ]);
                bf[1] = __float_as_uint(Ks[(nt * 8 + g) * 68 + kk + t + 4]);
                mma_tf32(Sa[nt], qf[kk8], bf);
            }
        }

        // ---- position encoding + causal mask ----
        if (LOCAL) {
            const int r0 = qrow + g, r1 = qrow + g + 8;
#pragma unroll
            for (int nt = 0; nt < 8; nt++) {
                Sa[nt][0] += pr0[nt].x; Sa[nt][1] += pr0[nt].y;
                Sa[nt][2] += pr1[nt].x; Sa[nt][3] += pr1[nt].y;
            }
            if (s0 + 63 > qrow) {
#pragma unroll
                for (int nt = 0; nt < 8; nt++) {
                    const int gc = s0 + nt * 8 + 2 * t;
                    if (gc     > r0) Sa[nt][0] = NEGINF;
                    if (gc + 1 > r0) Sa[nt][1] = NEGINF;
                    if (gc     > r1) Sa[nt][2] = NEGINF;
                    if (gc + 1 > r1) Sa[nt][3] = NEGINF;
                }
            }
        }

        // ---- online softmax in registers ----
        float mn0 = m0, mn1 = m1;
#pragma unroll
        for (int nt = 0; nt < 8; nt++) {
            mn0 = fmaxf(mn0, fmaxf(Sa[nt][0], Sa[nt][1]));
            mn1 = fmaxf(mn1, fmaxf(Sa[nt][2], Sa[nt][3]));
        }
        mn0 = fmaxf(mn0, __shfl_xor_sync(0xffffffffu, mn0, 1));
        mn0 = fmaxf(mn0, __shfl_xor_sync(0xffffffffu, mn0, 2));
        mn1 = fmaxf(mn1, __shfl_xor_sync(0xffffffffu, mn1, 1));
        mn1 = fmaxf(mn1, __shfl_xor_sync(0xffffffffu, mn1, 2));
        const float sc0 = __expf(m0 - mn0);
        const float sc1 = __expf(m1 - mn1);
        m0 = mn0; m1 = mn1;
        float sum0 = 0.f, sum1 = 0.f;
#pragma unroll
        for (int nt = 0; nt < 8; nt++) {
            float p0 = __expf(Sa[nt][0] - m0);
            float p1 = __expf(Sa[nt][1] - m0);
            float p2 = __expf(Sa[nt][2] - m1);
            float p3 = __expf(Sa[nt][3] - m1);
            sum0 += p0 + p1; sum1 += p2 + p3;
            Sa[nt][0] = p0; Sa[nt][1] = p1;   // raw fp32; HW truncates to tf32
            Sa[nt][2] = p2; Sa[nt][3] = p3;
        }
        l0 = l0 * sc0 + sum0;
        l1 = l1 * sc1 + sum1;

#pragma unroll
        for (int nt = 0; nt < 8; nt++) {
            O[nt][0] *= sc0; O[nt][1] *= sc0;
            O[nt][2] *= sc1; O[nt][3] *= sc1;
        }

        // ---- P to warp-private smem ----
        __syncwarp();
#pragma unroll
        for (int nt = 0; nt < 8; nt++) {
            const int c = nt * 8 + 2 * t;
            *(float2*)(Pw + g       * 68 + c) = make_float2(Sa[nt][0], Sa[nt][1]);
            *(float2*)(Pw + (g + 8) * 68 + c) = make_float2(Sa[nt][2], Sa[nt][3]);
        }
        __syncwarp();

        // ---- O += P V ----
#pragma unroll
        for (int kk8 = 0; kk8 < 8; kk8++) {
            const int kk = kk8 * 8;
            uint32_t af[4];
            af[0] = __float_as_uint(Pw[(g    ) * 68 + kk + t    ]);
            af[1] = __float_as_uint(Pw[(g + 8) * 68 + kk + t    ]);
            af[2] = __float_as_uint(Pw[(g    ) * 68 + kk + t + 4]);
            af[3] = __float_as_uint(Pw[(g + 8) * 68 + kk + t + 4]);
#pragma unroll
            for (int nt = 0; nt < 8; nt++) {
                uint32_t bf[2];
                bf[0] = __float_as_uint(Vt[VT(nt * 8 + g, kk + t    )]);
                bf[1] = __float_as_uint(Vt[VT(nt * 8 + g, kk + t + 4)]);
                mma_tf32(O[nt], af, bf);
            }
        }
    }

    // ---- epilogue ----
    l0 += __shfl_xor_sync(0xffffffffu, l0, 1);
    l0 += __shfl_xor_sync(0xffffffffu, l0, 2);
    l1 += __shfl_xor_sync(0xffffffffu, l1, 1);
    l1 += __shfl_xor_sync(0xffffffffu, l1, 2);

    const float gate = 1.f / (1.f + __expf(-memb[h]));
    const float wgt  = LOCAL ? (1.f - gate) : gate;
    const float li0 = wgt / l0;
    const float li1 = wgt / l1;

    const int r0 = qrow + g, r1 = qrow + g + 8;
#pragma unroll
    for (int nt = 0; nt < 8; nt++) {
        const int c = h * 64 + nt * 8 + 2 * t;
        const size_t i0 = ((size_t)r0 * BB + b) * E_DIM + c;
        const size_t i1 = ((size_t)r1 * BB + b) * E_DIM + c;
        *(float2*)(ctx + i0) = make_float2(O[nt][0] * li0, O[nt][1] * li0);
        *(float2*)(ctx + i1) = make_float2(O[nt][2] * li1, O[nt][3] * li1);
    }
}

// ---------------- launch ---------------------------------------------------
extern "C" void kernel_launch(void* const* d_in, const int* in_sizes, int n_in,
                              void* d_out, int out_size)
{
    const float* query = (const float*)d_in[0];
    const float* pos   = (const float*)d_in[1];
    const float* lcr   = (const float*)d_in[2];
    const float* q_w   = (const float*)d_in[3];
    const float* q_b   = (const float*)d_in[4];
    const float* k_w   = (const float*)d_in[5];
    const float* k_b   = (const float*)d_in[6];
    const float* v_w   = (const float*)d_in[7];
    const float* v_b   = (const float*)d_in[8];
    const float* out_w = (const float*)d_in[9];
    const float* out_b = (const float*)d_in[10];
    const float* memb  = (const float*)d_in[11];
    float* out = (float*)d_out;

    float *qp, *kp, *vp, *kmp, *vmp, *c1p, *c2p;
    cudaGetSymbolAddress((void**)&qp,  g_q);
    cudaGetSymbolAddress((void**)&kp,  g_k);
    cudaGetSymbolAddress((void**)&vp,  g_v);
    cudaGetSymbolAddress((void**)&kmp, g_km);
    cudaGetSymbolAddress((void**)&vmp, g_vm);
    cudaGetSymbolAddress((void**)&c1p, g_c1);
    cudaGetSymbolAddress((void**)&c2p, g_c2);

    const dim3 tpb(256);
    const int gsmem = 4 * GEMM_STG * (int)sizeof(float);  // 73728 B
    cudaFuncSetAttribute(gemm_proj,  cudaFuncAttributeMaxDynamicSharedMemorySize, gsmem);
    cudaFuncSetAttribute(gemm_out_k, cudaFuncAttributeMaxDynamicSharedMemorySize, gsmem);

    // 5 projections in one launch
    GC c0 = { query, q_w, q_b, qp, 0.125f, 32, T_LEN };
    GC c1 = { query, k_w, k_b, kp, 1.f,    32, T_LEN };
    GC c2 = { query, v_w, v_b, vp, 1.f,    32, T_LEN };
    GC c3 = { lcr,                              k_w, k_b, kmp, 1.f, 16, M_MEM };
    GC c4 = { lcr + (size_t)M_MEM * BB * E_DIM, v_w, v_b, vmp, 1.f, 16, M_MEM };
    gemm_proj<<<dim3(E_DIM / 128, 32, 5), tpb, gsmem>>>(c0, c1, c2, c3, c4);

    // fused attention (local + memory)
    const int asmem = (64 * 68 + 64 * 68 + 32 + 8 * 16 * 68) * (int)sizeof(float); // 69888 B
    cudaFuncSetAttribute(attn_fused, cudaFuncAttributeMaxDynamicSharedMemorySize, asmem);
    attn_fused<<<dim3(T_LEN / 128, H_NUM, 4), tpb, asmem>>>(
        qp, kp, vp, kmp, vmp, pos, memb, c1p, c2p);

    // output projection with fused ctx1 + ctx2
    gemm_out_k<<<dim3(E_DIM / 128, (T_LEN * BB) / 128), tpb, gsmem>>>(
        c1p, c2p, out_w, out_b, out);
}

// round 11
// speedup vs baseline: 2.4248x; 1.4013x over previous
#include <cuda_runtime.h>
#include <cuda_fp16.h>
#include <cstddef>
#include <cstdint>

#define T_LEN 2048
#define BB 2
#define E_DIM 1024
#define H_NUM 16
#define D_HEAD 64
#define M_MEM 1024
#define NEGINF -1e9f

// ---------------- scratch (device globals; allocation-free) ----------------
__device__ __half g_q  [(size_t)BB * H_NUM * T_LEN * D_HEAD];   // [b,h,t,d]
__device__ __half g_k  [(size_t)BB * H_NUM * T_LEN * D_HEAD];   // [b,h,s,d]
__device__ __half g_vt [(size_t)BB * H_NUM * D_HEAD * T_LEN];   // [b,h,d,s]
__device__ __half g_km [(size_t)BB * H_NUM * M_MEM * D_HEAD];   // [b,h,s,d]
__device__ __half g_vmt[(size_t)BB * H_NUM * D_HEAD * M_MEM];   // [b,h,d,s]
__device__ float  g_c1 [(size_t)T_LEN * BB * E_DIM];
__device__ float  g_c2 [(size_t)T_LEN * BB * E_DIM];

// ---------------- fp16 helpers ---------------------------------------------
__device__ __forceinline__ uint32_t f2h2(float a, float b) {
    __half2 h = __floats2half2_rn(a, b);
    return *(uint32_t*)&h;
}

__device__ __forceinline__ void mma_fp16(float* c, const uint32_t* a, const uint32_t* b) {
    asm volatile(
        "mma.sync.aligned.m16n8k16.row.col.f32.f16.f16.f32 "
        "{%0,%1,%2,%3}, {%4,%5,%6,%7}, {%8,%9}, {%0,%1,%2,%3};"
        : "+f"(c[0]), "+f"(c[1]), "+f"(c[2]), "+f"(c[3])
        : "r"(a[0]), "r"(a[1]), "r"(a[2]), "r"(a[3]), "r"(b[0]), "r"(b[1]));
}

// ---------------- fp16 GEMM: C = A * W^T + bias ----------------------------
// A: [Mrows,1024] fp32 row-major.  W: [1024,1024] fp32 row-major (out-feature
// major, k contiguous).  Smem stages hold half2-packed rows, stride GS u32.
// mode 0: fp32 out[r*1024+c]
// mode 1: half2-packed scatter to [b,h,t,d] (Q/K/Km style)
// mode 2: half scalar scatter to [b,h,d,t] (V transposed style)
#define GS 20                   // u32 per row (32 halves + pad)
#define GEMM_STG (128 * GS)     // u32 per matrix stage

struct GC {
    const float* A; const float* W; const float* bias; void* out;
    float scale; int ny; int Lrows; int mode;
};

__device__ __forceinline__ void gemm_body(
    const float* __restrict__ A, const float* __restrict__ A2,
    const float* __restrict__ W, const float* __restrict__ bias,
    void* __restrict__ out, float scale, int Lrows, int mode,
    uint32_t* gsm)
{
    uint32_t* Asb = gsm;
    uint32_t* Bsb = gsm + 2 * GEMM_STG;

    const int tid  = threadIdx.x;
    const int warp = tid >> 5;
    const int lane = tid & 31;
    const int g = lane >> 2, t = lane & 3;
    const int wm = warp >> 2;
    const int wn = warp & 3;
    const int row0 = blockIdx.y * 128;
    const int col0 = blockIdx.x * 128;

    const int lr = tid >> 1;           // 0..127
    const int lc = (tid & 1) * 16;     // float offset within 32-float chunk

    float acc[4][4][4];
#pragma unroll
    for (int mt = 0; mt < 4; mt++)
#pragma unroll
        for (int nt = 0; nt < 4; nt++)
#pragma unroll
            for (int i = 0; i < 4; i++) acc[mt][nt][i] = 0.f;

    const float* Ap  = A + (size_t)(row0 + lr) * E_DIM + lc;
    const float* A2p = A2 ? A2 + (size_t)(row0 + lr) * E_DIM + lc : nullptr;
    const float* Wp  = W + (size_t)(col0 + lr) * E_DIM + lc;

    float4 av[4], wv[4];
#pragma unroll
    for (int i = 0; i < 4; i++) {
        av[i] = *(const float4*)(Ap + i * 4);
        wv[i] = *(const float4*)(Wp + i * 4);
        if (A2p) {
            const float4 a2 = *(const float4*)(A2p + i * 4);
            av[i].x += a2.x; av[i].y += a2.y; av[i].z += a2.z; av[i].w += a2.w;
        }
    }
    {
        uint32_t* As = Asb;
        uint32_t* Bs = Bsb;
        const int sb = lr * GS + (tid & 1) * 8;
#pragma unroll
        for (int i = 0; i < 4; i++) {
            As[sb + 2*i    ] = f2h2(av[i].x, av[i].y);
            As[sb + 2*i + 1] = f2h2(av[i].z, av[i].w);
            Bs[sb + 2*i    ] = f2h2(wv[i].x, wv[i].y);
            Bs[sb + 2*i + 1] = f2h2(wv[i].z, wv[i].w);
        }
    }
    __syncthreads();

    for (int kt = 0; kt < E_DIM; kt += 32) {
        const int cur = (kt >> 5) & 1;
        const int nxt = cur ^ 1;
        const bool more = (kt + 32) < E_DIM;
        if (more) {
#pragma unroll
            for (int i = 0; i < 4; i++) {
                av[i] = *(const float4*)(Ap + kt + 32 + i * 4);
                wv[i] = *(const float4*)(Wp + kt + 32 + i * 4);
                if (A2p) {
                    const float4 a2 = *(const float4*)(A2p + kt + 32 + i * 4);
                    av[i].x += a2.x; av[i].y += a2.y; av[i].z += a2.z; av[i].w += a2.w;
                }
            }
        }

        const uint32_t* As = Asb + cur * GEMM_STG;
        const uint32_t* Bs = Bsb + cur * GEMM_STG;
#pragma unroll
        for (int ks = 0; ks < 2; ks++) {          // each ks = 16 k-values
            uint32_t af[4][4], bf[4][2];
#pragma unroll
            for (int mt = 0; mt < 4; mt++) {
                const int m = wm * 64 + mt * 16;
                af[mt][0] = As[(m + g    ) * GS + 8*ks + t    ];
                af[mt][1] = As[(m + g + 8) * GS + 8*ks + t    ];
                af[mt][2] = As[(m + g    ) * GS + 8*ks + t + 4];
                af[mt][3] = As[(m + g + 8) * GS + 8*ks + t + 4];
            }
#pragma unroll
            for (int nt = 0; nt < 4; nt++) {
                const int n = wn * 32 + nt * 8;
                bf[nt][0] = Bs[(n + g) * GS + 8*ks + t    ];
                bf[nt][1] = Bs[(n + g) * GS + 8*ks + t + 4];
            }
#pragma unroll
            for (int mt = 0; mt < 4; mt++)
#pragma unroll
                for (int nt = 0; nt < 4; nt++)
                    mma_fp16(acc[mt][nt], af[mt], bf[nt]);
        }

        if (more) {
            uint32_t* Asn = Asb + nxt * GEMM_STG;
            uint32_t* Bsn = Bsb + nxt * GEMM_STG;
            const int sb = lr * GS + (tid & 1) * 8;
#pragma unroll
            for (int i = 0; i < 4; i++) {
                Asn[sb + 2*i    ] = f2h2(av[i].x, av[i].y);
                Asn[sb + 2*i + 1] = f2h2(av[i].z, av[i].w);
                Bsn[sb + 2*i    ] = f2h2(wv[i].x, wv[i].y);
                Bsn[sb + 2*i + 1] = f2h2(wv[i].z, wv[i].w);
            }
        }
        __syncthreads();
    }

#pragma unroll
    for (int mt = 0; mt < 4; mt++) {
#pragma unroll
        for (int nt = 0; nt < 4; nt++) {
#pragma unroll
            for (int i = 0; i < 2; i++) {
                const int r  = row0 + wm * 64 + mt * 16 + g + i * 8;
                const int c0 = col0 + wn * 32 + nt * 8 + 2 * t;
                const float v0 = (acc[mt][nt][i * 2 + 0] + bias[c0    ]) * scale;
                const float v1 = (acc[mt][nt][i * 2 + 1] + bias[c0 + 1]) * scale;
                if (mode == 0) {
                    float* o = (float*)out + (size_t)r * E_DIM + c0;
                    o[0] = v0; o[1] = v1;
                } else {
                    const int tt = r >> 1, b = r & 1;
                    const int h = c0 >> 6, d = c0 & 63;
                    if (mode == 1) {
                        ((uint32_t*)out)[((((size_t)b * H_NUM + h) * Lrows + tt) * 64 + d) >> 1]
                            = f2h2(v0, v1);
                    } else {
                        __half* o = (__half*)out
                            + (((size_t)b * H_NUM + h) * 64 + d) * Lrows + tt;
                        o[0]     = __float2half_rn(v0);
                        o[Lrows] = __float2half_rn(v1);
                    }
                }
            }
        }
    }
}

__global__ void __launch_bounds__(256)
gemm_proj(GC c0, GC c1, GC c2, GC c3, GC c4)
{
    extern __shared__ uint32_t gsm[];
    const int z = blockIdx.z;
    GC c = c0;
    if (z == 1) c = c1; else if (z == 2) c = c2;
    else if (z == 3) c = c3; else if (z == 4) c = c4;
    if ((int)blockIdx.y >= c.ny) return;
    gemm_body(c.A, nullptr, c.W, c.bias, c.out, c.scale, c.Lrows, c.mode, gsm);
}

__global__ void __launch_bounds__(256)
gemm_out_k(const float* __restrict__ A, const float* __restrict__ A2,
           const float* __restrict__ W, const float* __restrict__ bias,
           float* __restrict__ out)
{
    extern __shared__ uint32_t gsm[];
    gemm_body(A, A2, W, bias, out, 1.f, T_LEN, 0, gsm);
}

// ---------------- fused attention (fp16 MMA, local + memory) ---------------
// grid (16, H, 4); z = kind*2 + b.  kind 0: local -> ctx1, 1: memory -> ctx2.
// CTA 128 q rows, 8 warps x 16 rows, 64-key tiles, register K/V prefetch.
// Smem (u32): Ks[64][36] (s,d halves) + Vt[64][36] (d,s halves) + Pw 8x[16][36].
#define AS 36

__global__ void __launch_bounds__(256, 1)
attn_fused(const __half* __restrict__ Qg,
           const __half* __restrict__ Kl, const __half* __restrict__ Vtl,
           const __half* __restrict__ Km, const __half* __restrict__ Vtm,
           const float* __restrict__ pos, const float* __restrict__ memb,
           float* __restrict__ ctx1, float* __restrict__ ctx2)
{
    extern __shared__ uint32_t smu[];
    uint32_t* Ks = smu;                 // 2304
    uint32_t* Vt = Ks + 64 * AS;        // 2304
    uint32_t* Ps = Vt + 64 * AS;        // 4608

    const int z    = blockIdx.z;
    const int kind = z >> 1;
    const int b    = z & 1;
    const bool LOCAL = (kind == 0);
    const __half* Kg  = LOCAL ? Kl  : Km;
    const __half* Vtg = LOCAL ? Vtl : Vtm;
    const int Skeys = LOCAL ? T_LEN : M_MEM;
    float* ctx = LOCAL ? ctx1 : ctx2;

    const int tid  = threadIdx.x;
    const int warp = tid >> 5;
    const int lane = tid & 31;
    const int g = lane >> 2, t = lane & 3;
    const int h  = blockIdx.y;
    const int t0 = blockIdx.x * 128;
    const int qrow = t0 + warp * 16;
    uint32_t* Pw = Ps + warp * 16 * AS;

    // ---- Q fragments (fp16 pairs), loaded once ----
    const uint32_t* Qu = (const uint32_t*)Qg
        + ((((size_t)b * H_NUM + h) * T_LEN + qrow) * D_HEAD >> 1);
    uint32_t qf[4][4];
#pragma unroll
    for (int ks = 0; ks < 4; ks++) {
        qf[ks][0] = Qu[(g    ) * 32 + 8*ks + t    ];
        qf[ks][1] = Qu[(g + 8) * 32 + 8*ks + t    ];
        qf[ks][2] = Qu[(g    ) * 32 + 8*ks + t + 4];
        qf[ks][3] = Qu[(g + 8) * 32 + 8*ks + t + 4];
    }

    // loader: thread owns row lr_ (s-row for K, d-row for Vt), 2 uint4 each
    const int lr_ = tid >> 2;           // 0..63
    const int lq  = (tid & 3) * 2;      // uint4 index 0..7 (2 each)
    const uint4* KuRow = (const uint4*)(Kg + ((size_t)b * H_NUM + h) * Skeys * D_HEAD)
                         + (size_t)lr_ * 8;                       // + s0*8 later
    const uint4* VuRow = (const uint4*)(Vtg + (((size_t)b * H_NUM + h) * D_HEAD + lr_) * Skeys);
                                                                  // + s0/8 later

    float m0 = -1e30f, m1 = -1e30f;
    float l0 = 0.f, l1 = 0.f;
    float O[8][4];
#pragma unroll
    for (int nt = 0; nt < 8; nt++)
#pragma unroll
        for (int i = 0; i < 4; i++) O[nt][i] = 0.f;

    const int send = LOCAL ? (t0 + 128) : Skeys;

    uint4 ka[2], va[2];
    ka[0] = KuRow[lq];     ka[1] = KuRow[lq + 1];
    va[0] = VuRow[lq];     va[1] = VuRow[lq + 1];

    for (int s0 = 0; s0 < send; s0 += 64) {
        const bool more = (s0 + 64) < send;

        __syncthreads();
        ((uint4*)(Ks + lr_ * AS))[lq]     = ka[0];
        ((uint4*)(Ks + lr_ * AS))[lq + 1] = ka[1];
        ((uint4*)(Vt + lr_ * AS))[lq]     = va[0];
        ((uint4*)(Vt + lr_ * AS))[lq + 1] = va[1];
        __syncthreads();

        if (more) {
            ka[0] = KuRow[(s0 + 64) * 8 + lq];
            ka[1] = KuRow[(s0 + 64) * 8 + lq + 1];
            va[0] = VuRow[(s0 + 64) / 8 + lq];
            va[1] = VuRow[(s0 + 64) / 8 + lq + 1];
        }

        if (LOCAL && s0 > qrow + 15) continue;   // fully-masked warp tile

        // prefetch position encoding
        float2 pr0[8], pr1[8];
        if (LOCAL) {
            const size_t pb0 = ((size_t)h * T_LEN + qrow + g    ) * (size_t)T_LEN + s0;
            const size_t pb1 = ((size_t)h * T_LEN + qrow + g + 8) * (size_t)T_LEN + s0;
#pragma unroll
            for (int nt = 0; nt < 8; nt++) {
                pr0[nt] = *(const float2*)(pos + pb0 + nt * 8 + 2 * t);
                pr1[nt] = *(const float2*)(pos + pb1 + nt * 8 + 2 * t);
            }
        }

        // ---- S = Q K^T : 4 k16-steps x 8 n-tiles ----
        float Sa[8][4];
#pragma unroll
        for (int nt = 0; nt < 8; nt++)
#pragma unroll
            for (int i = 0; i < 4; i++) Sa[nt][i] = 0.f;
#pragma unroll
        for (int ks = 0; ks < 4; ks++) {
#pragma unroll
            for (int nt = 0; nt < 8; nt++) {
                uint32_t bf[2];
                bf[0] = Ks[(nt * 8 + g) * AS + 8*ks + t    ];
                bf[1] = Ks[(nt * 8 + g) * AS + 8*ks + t + 4];
                mma_fp16(Sa[nt], qf[ks], bf);
            }
        }

        // ---- position encoding + causal mask ----
        if (LOCAL) {
            const int r0 = qrow + g, r1 = qrow + g + 8;
#pragma unroll
            for (int nt = 0; nt < 8; nt++) {
                Sa[nt][0] += pr0[nt].x; Sa[nt][1] += pr0[nt].y;
                Sa[nt][2] += pr1[nt].x; Sa[nt][3] += pr1[nt].y;
            }
            if (s0 + 63 > qrow) {
#pragma unroll
                for (int nt = 0; nt < 8; nt++) {
                    const int gc = s0 + nt * 8 + 2 * t;
                    if (gc     > r0) Sa[nt][0] = NEGINF;
                    if (gc + 1 > r0) Sa[nt][1] = NEGINF;
                    if (gc     > r1) Sa[nt][2] = NEGINF;
                    if (gc + 1 > r1) Sa[nt][3] = NEGINF;
                }
            }
        }

        // ---- online softmax in registers ----
        float mn0 = m0, mn1 = m1;
#pragma unroll
        for (int nt = 0; nt < 8; nt++) {
            mn0 = fmaxf(mn0, fmaxf(Sa[nt][0], Sa[nt][1]));
            mn1 = fmaxf(mn1, fmaxf(Sa[nt][2], Sa[nt][3]));
        }
        mn0 = fmaxf(mn0, __shfl_xor_sync(0xffffffffu, mn0, 1));
        mn0 = fmaxf(mn0, __shfl_xor_sync(0xffffffffu, mn0, 2));
        mn1 = fmaxf(mn1, __shfl_xor_sync(0xffffffffu, mn1, 1));
        mn1 = fmaxf(mn1, __shfl_xor_sync(0xffffffffu, mn1, 2));
        const float sc0 = __expf(m0 - mn0);
        const float sc1 = __expf(m1 - mn1);
        m0 = mn0; m1 = mn1;
        float sum0 = 0.f, sum1 = 0.f;
        uint32_t ph[8][2];
#pragma unroll
        for (int nt = 0; nt < 8; nt++) {
            const float p0 = __expf(Sa[nt][0] - m0);
            const float p1 = __expf(Sa[nt][1] - m0);
            const float p2 = __expf(Sa[nt][2] - m1);
            const float p3 = __expf(Sa[nt][3] - m1);
            sum0 += p0 + p1; sum1 += p2 + p3;
            ph[nt][0] = f2h2(p0, p1);
            ph[nt][1] = f2h2(p2, p3);
        }
        l0 = l0 * sc0 + sum0;
        l1 = l1 * sc1 + sum1;

#pragma unroll
        for (int nt = 0; nt < 8; nt++) {
            O[nt][0] *= sc0; O[nt][1] *= sc0;
            O[nt][2] *= sc1; O[nt][3] *= sc1;
        }

        // ---- P (half2 pairs) to warp-private smem ----
        __syncwarp();
#pragma unroll
        for (int nt = 0; nt < 8; nt++) {
            Pw[(g    ) * AS + nt * 4 + t] = ph[nt][0];
            Pw[(g + 8) * AS + nt * 4 + t] = ph[nt][1];
        }
        __syncwarp();

        // ---- O += P V : 4 k16-steps x 8 n-tiles ----
#pragma unroll
        for (int ks = 0; ks < 4; ks++) {
            uint32_t af[4];
            af[0] = Pw[(g    ) * AS + 8*ks + t    ];
            af[1] = Pw[(g + 8) * AS + 8*ks + t    ];
            af[2] = Pw[(g    ) * AS + 8*ks + t + 4];
            af[3] = Pw[(g + 8) * AS + 8*ks + t + 4];
#pragma unroll
            for (int nt = 0; nt < 8; nt++) {
                uint32_t bf[2];
                bf[0] = Vt[(nt * 8 + g) * AS + 8*ks + t    ];
                bf[1] = Vt[(nt * 8 + g) * AS + 8*ks + t + 4];
                mma_fp16(O[nt], af, bf);
            }
        }
    }

    // ---- epilogue ----
    l0 += __shfl_xor_sync(0xffffffffu, l0, 1);
    l0 += __shfl_xor_sync(0xffffffffu, l0, 2);
    l1 += __shfl_xor_sync(0xffffffffu, l1, 1);
    l1 += __shfl_xor_sync(0xffffffffu, l1, 2);

    const float gate = 1.f / (1.f + __expf(-memb[h]));
    const float wgt  = LOCAL ? (1.f - gate) : gate;
    const float li0 = wgt / l0;
    const float li1 = wgt / l1;

    const int r0 = qrow + g, r1 = qrow + g + 8;
#pragma unroll
    for (int nt = 0; nt < 8; nt++) {
        const int c = h * 64 + nt * 8 + 2 * t;
        const size_t i0 = ((size_t)r0 * BB + b) * E_DIM + c;
        const size_t i1 = ((size_t)r1 * BB + b) * E_DIM + c;
        *(float2*)(ctx + i0) = make_float2(O[nt][0] * li0, O[nt][1] * li0);
        *(float2*)(ctx + i1) = make_float2(O[nt][2] * li1, O[nt][3] * li1);
    }
}

// ---------------- launch ---------------------------------------------------
extern "C" void kernel_launch(void* const* d_in, const int* in_sizes, int n_in,
                              void* d_out, int out_size)
{
    const float* query = (const float*)d_in[0];
    const float* pos   = (const float*)d_in[1];
    const float* lcr   = (const float*)d_in[2];
    const float* q_w   = (const float*)d_in[3];
    const float* q_b   = (const float*)d_in[4];
    const float* k_w   = (const float*)d_in[5];
    const float* k_b   = (const float*)d_in[6];
    const float* v_w   = (const float*)d_in[7];
    const float* v_b   = (const float*)d_in[8];
    const float* out_w = (const float*)d_in[9];
    const float* out_b = (const float*)d_in[10];
    const float* memb  = (const float*)d_in[11];
    float* out = (float*)d_out;

    void *qp, *kp, *vtp, *kmp, *vmtp;
    float *c1p, *c2p;
    cudaGetSymbolAddress(&qp,   g_q);
    cudaGetSymbolAddress(&kp,   g_k);
    cudaGetSymbolAddress(&vtp,  g_vt);
    cudaGetSymbolAddress(&kmp,  g_km);
    cudaGetSymbolAddress(&vmtp, g_vmt);
    cudaGetSymbolAddress((void**)&c1p, g_c1);
    cudaGetSymbolAddress((void**)&c2p, g_c2);

    const dim3 tpb(256);
    const int gsmem = 4 * GEMM_STG * (int)sizeof(uint32_t);  // 40960 B

    // 5 projections in one launch (Q/K/Km packed half2; V/Vm transposed half)
    GC c0 = { query, q_w, q_b, qp,   0.125f, 32, T_LEN, 1 };
    GC c1 = { query, k_w, k_b, kp,   1.f,    32, T_LEN, 1 };
    GC c2 = { query, v_w, v_b, vtp,  1.f,    32, T_LEN, 2 };
    GC c3 = { lcr,                              k_w, k_b, kmp,  1.f, 16, M_MEM, 1 };
    GC c4 = { lcr + (size_t)M_MEM * BB * E_DIM, v_w, v_b, vmtp, 1.f, 16, M_MEM, 2 };
    gemm_proj<<<dim3(E_DIM / 128, 32, 5), tpb, gsmem>>>(c0, c1, c2, c3, c4);

    // fused attention (local + memory)
    const int asmem = (2 * 64 * AS + 8 * 16 * AS) * (int)sizeof(uint32_t);  // 36864 B
    attn_fused<<<dim3(T_LEN / 128, H_NUM, 4), tpb, asmem>>>(
        (const __half*)qp, (const __half*)kp, (const __half*)vtp,
        (const __half*)kmp, (const __half*)vmtp, pos, memb, c1p, c2p);

    // output projection with fused ctx1 + ctx2
    gemm_out_k<<<dim3(E_DIM / 128, (T_LEN * BB) / 128), tpb, gsmem>>>(
        c1p, c2p, out_w, out_b, out);
}

// round 14
// speedup vs baseline: 2.7637x; 1.1398x over previous
#include <cuda_runtime.h>
#include <cuda_fp16.h>
#include <cstddef>
#include <cstdint>

#define T_LEN 2048
#define BB 2
#define E_DIM 1024
#define H_NUM 16
#define D_HEAD 64
#define M_MEM 1024
#define NEGINF -1e9f

// ---------------- scratch (device globals; allocation-free) ----------------
__device__ __half g_q  [(size_t)BB * H_NUM * T_LEN * D_HEAD];   // [b,h,t,d]
__device__ __half g_k  [(size_t)BB * H_NUM * T_LEN * D_HEAD];   // [b,h,s,d]
__device__ __half g_vt [(size_t)BB * H_NUM * D_HEAD * T_LEN];   // [b,h,d,s]
__device__ __half g_km [(size_t)BB * H_NUM * M_MEM * D_HEAD];   // [b,h,s,d]
__device__ __half g_vmt[(size_t)BB * H_NUM * D_HEAD * M_MEM];   // [b,h,d,s]
__device__ float  g_c1 [(size_t)T_LEN * BB * E_DIM];
__device__ float  g_c2 [(size_t)T_LEN * BB * E_DIM];
// fp16 copies of fp32 inputs (pre-converted once per call)
__device__ __half g_hx [(size_t)T_LEN * BB * E_DIM];            // query
__device__ __half g_hl [(size_t)2 * M_MEM * BB * E_DIM];        // lcr (both)
__device__ __half g_hqw[(size_t)E_DIM * E_DIM];
__device__ __half g_hkw[(size_t)E_DIM * E_DIM];
__device__ __half g_hvw[(size_t)E_DIM * E_DIM];

// ---------------- fp16 helpers ---------------------------------------------
__device__ __forceinline__ uint32_t f2h2(float a, float b) {
    __half2 h = __floats2half2_rn(a, b);
    return *(uint32_t*)&h;
}

__device__ __forceinline__ void mma_fp16(float* c, const uint32_t* a, const uint32_t* b) {
    asm volatile(
        "mma.sync.aligned.m16n8k16.row.col.f32.f16.f16.f32 "
        "{%0,%1,%2,%3}, {%4,%5,%6,%7}, {%8,%9}, {%0,%1,%2,%3};"
        : "+f"(c[0]), "+f"(c[1]), "+f"(c[2]), "+f"(c[3])
        : "r"(a[0]), "r"(a[1]), "r"(a[2]), "r"(a[3]), "r"(b[0]), "r"(b[1]));
}

// ---------------- fp32 -> fp16 conversion pass -----------------------------
struct CS { const float4* s; uint4* d; int n8; };

__global__ void __launch_bounds__(256)
cvt_k(CS c0, CS c1, CS c2, CS c3, CS c4)
{
    CS c = c0;
    const int z = blockIdx.y;
    if (z == 1) c = c1; else if (z == 2) c = c2;
    else if (z == 3) c = c3; else if (z == 4) c = c4;
    const int i = blockIdx.x * 256 + threadIdx.x;
    if (i >= c.n8) return;
    const float4 a = c.s[2 * i];
    const float4 b = c.s[2 * i + 1];
    c.d[i] = make_uint4(f2h2(a.x, a.y), f2h2(a.z, a.w),
                        f2h2(b.x, b.y), f2h2(b.z, b.w));
}

// ---------------- fp16 HGEMM (projections): C = A * W^T + bias -------------
// A: [Mrows,1024] fp16 row-major.  W: [1024,1024] fp16 row-major.
// mode 1: half2-packed scatter to [b,h,t,d];  mode 2: [b,h,d,t] transposed.
#define GS 20                   // u32 per row (32 halves + pad)
#define GEMM_STG (128 * GS)     // u32 per matrix stage

struct HGC {
    const __half* A; const __half* W; const float* bias; void* out;
    float scale; int ny; int Lrows; int mode;
};

__global__ void __launch_bounds__(256, 2)
gemm_proj(HGC c0, HGC c1, HGC c2, HGC c3, HGC c4)
{
    extern __shared__ uint32_t gsm[];
    HGC c = c0;
    {
        const int z = blockIdx.z;
        if (z == 1) c = c1; else if (z == 2) c = c2;
        else if (z == 3) c = c3; else if (z == 4) c = c4;
    }
    if ((int)blockIdx.y >= c.ny) return;

    uint32_t* Asb = gsm;
    uint32_t* Bsb = gsm + 2 * GEMM_STG;

    const int tid  = threadIdx.x;
    const int warp = tid >> 5;
    const int lane = tid & 31;
    const int g = lane >> 2, t = lane & 3;
    const int wm = warp >> 2;
    const int wn = warp & 3;
    const int row0 = blockIdx.y * 128;
    const int col0 = blockIdx.x * 128;

    const int lr = tid >> 1;           // 0..127
    const int hc = (tid & 1) * 2;      // uint4 offset within row chunk

    float acc[4][4][4];
#pragma unroll
    for (int mt = 0; mt < 4; mt++)
#pragma unroll
        for (int nt = 0; nt < 4; nt++)
#pragma unroll
            for (int i = 0; i < 4; i++) acc[mt][nt][i] = 0.f;

    const uint4* Ap = (const uint4*)(c.A + (size_t)(row0 + lr) * E_DIM) + hc;
    const uint4* Wp = (const uint4*)(c.W + (size_t)(col0 + lr) * E_DIM) + hc;

    // prologue: chunk 0
    uint4 a0 = Ap[0], a1 = Ap[1];
    uint4 w0 = Wp[0], w1 = Wp[1];
    {
        uint4* da = (uint4*)(Asb + lr * GS) + hc;
        uint4* db = (uint4*)(Bsb + lr * GS) + hc;
        da[0] = a0; da[1] = a1;
        db[0] = w0; db[1] = w1;
    }
    __syncthreads();

    for (int kt = 0; kt < E_DIM; kt += 32) {
        const int cur = (kt >> 5) & 1;
        const int nxt = cur ^ 1;
        const bool more = (kt + 32) < E_DIM;
        if (more) {
            const int ku = (kt + 32) >> 3;   // uint4 index of next chunk
            a0 = Ap[ku]; a1 = Ap[ku + 1];
            w0 = Wp[ku]; w1 = Wp[ku + 1];
        }

        const uint32_t* As = Asb + cur * GEMM_STG;
        const uint32_t* Bs = Bsb + cur * GEMM_STG;
#pragma unroll
        for (int ks = 0; ks < 2; ks++) {          // each ks = 16 k-values
            uint32_t af[4][4], bf[4][2];
#pragma unroll
            for (int mt = 0; mt < 4; mt++) {
                const int m = wm * 64 + mt * 16;
                af[mt][0] = As[(m + g    ) * GS + 8*ks + t    ];
                af[mt][1] = As[(m + g + 8) * GS + 8*ks + t    ];
                af[mt][2] = As[(m + g    ) * GS + 8*ks + t + 4];
                af[mt][3] = As[(m + g + 8) * GS + 8*ks + t + 4];
            }
#pragma unroll
            for (int nt = 0; nt < 4; nt++) {
                const int n = wn * 32 + nt * 8;
                bf[nt][0] = Bs[(n + g) * GS + 8*ks + t    ];
                bf[nt][1] = Bs[(n + g) * GS + 8*ks + t + 4];
            }
#pragma unroll
            for (int mt = 0; mt < 4; mt++)
#pragma unroll
                for (int nt = 0; nt < 4; nt++)
                    mma_fp16(acc[mt][nt], af[mt], bf[nt]);
        }

        if (more) {
            uint4* da = (uint4*)(Asb + nxt * GEMM_STG + lr * GS) + hc;
            uint4* db = (uint4*)(Bsb + nxt * GEMM_STG + lr * GS) + hc;
            da[0] = a0; da[1] = a1;
            db[0] = w0; db[1] = w1;
        }
        __syncthreads();
    }

#pragma unroll
    for (int mt = 0; mt < 4; mt++) {
#pragma unroll
        for (int nt = 0; nt < 4; nt++) {
#pragma unroll
            for (int i = 0; i < 2; i++) {
                const int r  = row0 + wm * 64 + mt * 16 + g + i * 8;
                const int c0i = col0 + wn * 32 + nt * 8 + 2 * t;
                const float v0 = (acc[mt][nt][i * 2 + 0] + c.bias[c0i    ]) * c.scale;
                const float v1 = (acc[mt][nt][i * 2 + 1] + c.bias[c0i + 1]) * c.scale;
                const int tt = r >> 1, b = r & 1;
                const int h = c0i >> 6, d = c0i & 63;
                if (c.mode == 1) {
                    ((uint32_t*)c.out)[((((size_t)b * H_NUM + h) * c.Lrows + tt) * 64 + d) >> 1]
                        = f2h2(v0, v1);
                } else {
                    __half* o = (__half*)c.out
                        + (((size_t)b * H_NUM + h) * 64 + d) * c.Lrows + tt;
                    o[0]        = __float2half_rn(v0);
                    o[c.Lrows]  = __float2half_rn(v1);
                }
            }
        }
    }
}

// ---------------- fp32-input GEMM (output projection) ----------------------
__global__ void __launch_bounds__(256)
gemm_out_k(const float* __restrict__ A, const float* __restrict__ A2,
           const float* __restrict__ W, const float* __restrict__ bias,
           float* __restrict__ out)
{
    extern __shared__ uint32_t gsm[];
    uint32_t* Asb = gsm;
    uint32_t* Bsb = gsm + 2 * GEMM_STG;

    const int tid  = threadIdx.x;
    const int warp = tid >> 5;
    const int lane = tid & 31;
    const int g = lane >> 2, t = lane & 3;
    const int wm = warp >> 2;
    const int wn = warp & 3;
    const int row0 = blockIdx.y * 128;
    const int col0 = blockIdx.x * 128;

    const int lr = tid >> 1;
    const int lc = (tid & 1) * 16;

    float acc[4][4][4];
#pragma unroll
    for (int mt = 0; mt < 4; mt++)
#pragma unroll
        for (int nt = 0; nt < 4; nt++)
#pragma unroll
            for (int i = 0; i < 4; i++) acc[mt][nt][i] = 0.f;

    const float* Ap  = A  + (size_t)(row0 + lr) * E_DIM + lc;
    const float* A2p = A2 + (size_t)(row0 + lr) * E_DIM + lc;
    const float* Wp  = W  + (size_t)(col0 + lr) * E_DIM + lc;

    float4 av[4], wv[4];
#pragma unroll
    for (int i = 0; i < 4; i++) {
        av[i] = *(const float4*)(Ap + i * 4);
        wv[i] = *(const float4*)(Wp + i * 4);
        const float4 a2 = *(const float4*)(A2p + i * 4);
        av[i].x += a2.x; av[i].y += a2.y; av[i].z += a2.z; av[i].w += a2.w;
    }
    {
        const int sb = lr * GS + (tid & 1) * 8;
#pragma unroll
        for (int i = 0; i < 4; i++) {
            Asb[sb + 2*i    ] = f2h2(av[i].x, av[i].y);
            Asb[sb + 2*i + 1] = f2h2(av[i].z, av[i].w);
            Bsb[sb + 2*i    ] = f2h2(wv[i].x, wv[i].y);
            Bsb[sb + 2*i + 1] = f2h2(wv[i].z, wv[i].w);
        }
    }
    __syncthreads();

    for (int kt = 0; kt < E_DIM; kt += 32) {
        const int cur = (kt >> 5) & 1;
        const int nxt = cur ^ 1;
        const bool more = (kt + 32) < E_DIM;
        if (more) {
#pragma unroll
            for (int i = 0; i < 4; i++) {
                av[i] = *(const float4*)(Ap + kt + 32 + i * 4);
                wv[i] = *(const float4*)(Wp + kt + 32 + i * 4);
                const float4 a2 = *(const float4*)(A2p + kt + 32 + i * 4);
                av[i].x += a2.x; av[i].y += a2.y; av[i].z += a2.z; av[i].w += a2.w;
            }
        }

        const uint32_t* As = Asb + cur * GEMM_STG;
        const uint32_t* Bs = Bsb + cur * GEMM_STG;
#pragma unroll
        for (int ks = 0; ks < 2; ks++) {
            uint32_t af[4][4], bf[4][2];
#pragma unroll
            for (int mt = 0; mt < 4; mt++) {
                const int m = wm * 64 + mt * 16;
                af[mt][0] = As[(m + g    ) * GS + 8*ks + t    ];
                af[mt][1] = As[(m + g + 8) * GS + 8*ks + t    ];
                af[mt][2] = As[(m + g    ) * GS + 8*ks + t + 4];
                af[mt][3] = As[(m + g + 8) * GS + 8*ks + t + 4];
            }
#pragma unroll
            for (int nt = 0; nt < 4; nt++) {
                const int n = wn * 32 + nt * 8;
                bf[nt][0] = Bs[(n + g) * GS + 8*ks + t    ];
                bf[nt][1] = Bs[(n + g) * GS + 8*ks + t + 4];
            }
#pragma unroll
            for (int mt = 0; mt < 4; mt++)
#pragma unroll
                for (int nt = 0; nt < 4; nt++)
                    mma_fp16(acc[mt][nt], af[mt], bf[nt]);
        }

        if (more) {
            const int sb = nxt * GEMM_STG + lr * GS + (tid & 1) * 8;
#pragma unroll
            for (int i = 0; i < 4; i++) {
                Asb[sb + 2*i    ] = f2h2(av[i].x, av[i].y);
                Asb[sb + 2*i + 1] = f2h2(av[i].z, av[i].w);
                Bsb[sb + 2*i    ] = f2h2(wv[i].x, wv[i].y);
                Bsb[sb + 2*i + 1] = f2h2(wv[i].z, wv[i].w);
            }
        }
        __syncthreads();
    }

#pragma unroll
    for (int mt = 0; mt < 4; mt++) {
#pragma unroll
        for (int nt = 0; nt < 4; nt++) {
#pragma unroll
            for (int i = 0; i < 2; i++) {
                const int r  = row0 + wm * 64 + mt * 16 + g + i * 8;
                const int c0 = col0 + wn * 32 + nt * 8 + 2 * t;
                float* o = out + (size_t)r * E_DIM + c0;
                o[0] = acc[mt][nt][i * 2 + 0] + bias[c0];
                o[1] = acc[mt][nt][i * 2 + 1] + bias[c0 + 1];
            }
        }
    }
}

// ---------------- fused attention (fp16 MMA, local + memory) ---------------
#define AS 36

__global__ void __launch_bounds__(256, 1)
attn_fused(const __half* __restrict__ Qg,
           const __half* __restrict__ Kl, const __half* __restrict__ Vtl,
           const __half* __restrict__ Km, const __half* __restrict__ Vtm,
           const float* __restrict__ pos, const float* __restrict__ memb,
           float* __restrict__ ctx1, float* __restrict__ ctx2)
{
    extern __shared__ uint32_t smu[];
    uint32_t* Ks = smu;
    uint32_t* Vt = Ks + 64 * AS;
    uint32_t* Ps = Vt + 64 * AS;

    const int z    = blockIdx.z;
    const int kind = z >> 1;
    const int b    = z & 1;
    const bool LOCAL = (kind == 0);
    const __half* Kg  = LOCAL ? Kl  : Km;
    const __half* Vtg = LOCAL ? Vtl : Vtm;
    const int Skeys = LOCAL ? T_LEN : M_MEM;
    float* ctx = LOCAL ? ctx1 : ctx2;

    const int tid  = threadIdx.x;
    const int warp = tid >> 5;
    const int lane = tid & 31;
    const int g = lane >> 2, t = lane & 3;
    const int h  = blockIdx.y;
    const int t0 = blockIdx.x * 128;
    const int qrow = t0 + warp * 16;
    uint32_t* Pw = Ps + warp * 16 * AS;

    const uint32_t* Qu = (const uint32_t*)Qg
        + ((((size_t)b * H_NUM + h) * T_LEN + qrow) * D_HEAD >> 1);
    uint32_t qf[4][4];
#pragma unroll
    for (int ks = 0; ks < 4; ks++) {
        qf[ks][0] = Qu[(g    ) * 32 + 8*ks + t    ];
        qf[ks][1] = Qu[(g + 8) * 32 + 8*ks + t    ];
        qf[ks][2] = Qu[(g    ) * 32 + 8*ks + t + 4];
        qf[ks][3] = Qu[(g + 8) * 32 + 8*ks + t + 4];
    }

    const int lr_ = tid >> 2;
    const int lq  = (tid & 3) * 2;
    const uint4* KuRow = (const uint4*)(Kg + ((size_t)b * H_NUM + h) * Skeys * D_HEAD)
                         + (size_t)lr_ * 8;
    const uint4* VuRow = (const uint4*)(Vtg + (((size_t)b * H_NUM + h) * D_HEAD + lr_) * Skeys);

    float m0 = -1e30f, m1 = -1e30f;
    float l0 = 0.f, l1 = 0.f;
    float O[8][4];
#pragma unroll
    for (int nt = 0; nt < 8; nt++)
#pragma unroll
        for (int i = 0; i < 4; i++) O[nt][i] = 0.f;

    const int send = LOCAL ? (t0 + 128) : Skeys;

    uint4 ka[2], va[2];
    ka[0] = KuRow[lq];     ka[1] = KuRow[lq + 1];
    va[0] = VuRow[lq];     va[1] = VuRow[lq + 1];

    for (int s0 = 0; s0 < send; s0 += 64) {
        const bool more = (s0 + 64) < send;

        __syncthreads();
        ((uint4*)(Ks + lr_ * AS))[lq]     = ka[0];
        ((uint4*)(Ks + lr_ * AS))[lq + 1] = ka[1];
        ((uint4*)(Vt + lr_ * AS))[lq]     = va[0];
        ((uint4*)(Vt + lr_ * AS))[lq + 1] = va[1];
        __syncthreads();

        if (more) {
            ka[0] = KuRow[(s0 + 64) * 8 + lq];
            ka[1] = KuRow[(s0 + 64) * 8 + lq + 1];
            va[0] = VuRow[(s0 + 64) / 8 + lq];
            va[1] = VuRow[(s0 + 64) / 8 + lq + 1];
        }

        if (LOCAL && s0 > qrow + 15) continue;

        float2 pr0[8], pr1[8];
        if (LOCAL) {
            const size_t pb0 = ((size_t)h * T_LEN + qrow + g    ) * (size_t)T_LEN + s0;
            const size_t pb1 = ((size_t)h * T_LEN + qrow + g + 8) * (size_t)T_LEN + s0;
#pragma unroll
            for (int nt = 0; nt < 8; nt++) {
                pr0[nt] = *(const float2*)(pos + pb0 + nt * 8 + 2 * t);
                pr1[nt] = *(const float2*)(pos + pb1 + nt * 8 + 2 * t);
            }
        }

        float Sa[8][4];
#pragma unroll
        for (int nt = 0; nt < 8; nt++)
#pragma unroll
            for (int i = 0; i < 4; i++) Sa[nt][i] = 0.f;
#pragma unroll
        for (int ks = 0; ks < 4; ks++) {
#pragma unroll
            for (int nt = 0; nt < 8; nt++) {
                uint32_t bf[2];
                bf[0] = Ks[(nt * 8 + g) * AS + 8*ks + t    ];
                bf[1] = Ks[(nt * 8 + g) * AS + 8*ks + t + 4];
                mma_fp16(Sa[nt], qf[ks], bf);
            }
        }

        if (LOCAL) {
            const int r0 = qrow + g, r1 = qrow + g + 8;
#pragma unroll
            for (int nt = 0; nt < 8; nt++) {
                Sa[nt][0] += pr0[nt].x; Sa[nt][1] += pr0[nt].y;
                Sa[nt][2] += pr1[nt].x; Sa[nt][3] += pr1[nt].y;
            }
            if (s0 + 63 > qrow) {
#pragma unroll
                for (int nt = 0; nt < 8; nt++) {
                    const int gc = s0 + nt * 8 + 2 * t;
                    if (gc     > r0) Sa[nt][0] = NEGINF;
                    if (gc + 1 > r0) Sa[nt][1] = NEGINF;
                    if (gc     > r1) Sa[nt][2] = NEGINF;
                    if (gc + 1 > r1) Sa[nt][3] = NEGINF;
                }
            }
        }

        float mn0 = m0, mn1 = m1;
#pragma unroll
        for (int nt = 0; nt < 8; nt++) {
            mn0 = fmaxf(mn0, fmaxf(Sa[nt][0], Sa[nt][1]));
            mn1 = fmaxf(mn1, fmaxf(Sa[nt][2], Sa[nt][3]));
        }
        mn0 = fmaxf(mn0, __shfl_xor_sync(0xffffffffu, mn0, 1));
        mn0 = fmaxf(mn0, __shfl_xor_sync(0xffffffffu, mn0, 2));
        mn1 = fmaxf(mn1, __shfl_xor_sync(0xffffffffu, mn1, 1));
        mn1 = fmaxf(mn1, __shfl_xor_sync(0xffffffffu, mn1, 2));
        const float sc0 = __expf(m0 - mn0);
        const float sc1 = __expf(m1 - mn1);
        m0 = mn0; m1 = mn1;
        float sum0 = 0.f, sum1 = 0.f;
        uint32_t ph[8][2];
#pragma unroll
        for (int nt = 0; nt < 8; nt++) {
            const float p0 = __expf(Sa[nt][0] - m0);
            const float p1 = __expf(Sa[nt][1] - m0);
            const float p2 = __expf(Sa[nt][2] - m1);
            const float p3 = __expf(Sa[nt][3] - m1);
            sum0 += p0 + p1; sum1 += p2 + p3;
            ph[nt][0] = f2h2(p0, p1);
            ph[nt][1] = f2h2(p2, p3);
        }
        l0 = l0 * sc0 + sum0;
        l1 = l1 * sc1 + sum1;

#pragma unroll
        for (int nt = 0; nt < 8; nt++) {
            O[nt][0] *= sc0; O[nt][1] *= sc0;
            O[nt][2] *= sc1; O[nt][3] *= sc1;
        }

        __syncwarp();
#pragma unroll
        for (int nt = 0; nt < 8; nt++) {
            Pw[(g    ) * AS + nt * 4 + t] = ph[nt][0];
            Pw[(g + 8) * AS + nt * 4 + t] = ph[nt][1];
        }
        __syncwarp();

#pragma unroll
        for (int ks = 0; ks < 4; ks++) {
            uint32_t af[4];
            af[0] = Pw[(g    ) * AS + 8*ks + t    ];
            af[1] = Pw[(g + 8) * AS + 8*ks + t    ];
            af[2] = Pw[(g    ) * AS + 8*ks + t + 4];
            af[3] = Pw[(g + 8) * AS + 8*ks + t + 4];
#pragma unroll
            for (int nt = 0; nt < 8; nt++) {
                uint32_t bf[2];
                bf[0] = Vt[(nt * 8 + g) * AS + 8*ks + t    ];
                bf[1] = Vt[(nt * 8 + g) * AS + 8*ks + t + 4];
                mma_fp16(O[nt], af, bf);
            }
        }
    }

    l0 += __shfl_xor_sync(0xffffffffu, l0, 1);
    l0 += __shfl_xor_sync(0xffffffffu, l0, 2);
    l1 += __shfl_xor_sync(0xffffffffu, l1, 1);
    l1 += __shfl_xor_sync(0xffffffffu, l1, 2);

    const float gate = 1.f / (1.f + __expf(-memb[h]));
    const float wgt  = LOCAL ? (1.f - gate) : gate;
    const float li0 = wgt / l0;
    const float li1 = wgt / l1;

    const int r0 = qrow + g, r1 = qrow + g + 8;
#pragma unroll
    for (int nt = 0; nt < 8; nt++) {
        const int c = h * 64 + nt * 8 + 2 * t;
        const size_t i0 = ((size_t)r0 * BB + b) * E_DIM + c;
        const size_t i1 = ((size_t)r1 * BB + b) * E_DIM + c;
        *(float2*)(ctx + i0) = make_float2(O[nt][0] * li0, O[nt][1] * li0);
        *(float2*)(ctx + i1) = make_float2(O[nt][2] * li1, O[nt][3] * li1);
    }
}

// ---------------- launch ---------------------------------------------------
extern "C" void kernel_launch(void* const* d_in, const int* in_sizes, int n_in,
                              void* d_out, int out_size)
{
    const float* query = (const float*)d_in[0];
    const float* pos   = (const float*)d_in[1];
    const float* lcr   = (const float*)d_in[2];
    const float* q_w   = (const float*)d_in[3];
    const float* q_b   = (const float*)d_in[4];
    const float* k_w   = (const float*)d_in[5];
    const float* k_b   = (const float*)d_in[6];
    const float* v_w   = (const float*)d_in[7];
    const float* v_b   = (const float*)d_in[8];
    const float* out_w = (const float*)d_in[9];
    const float* out_b = (const float*)d_in[10];
    const float* memb  = (const float*)d_in[11];
    float* out = (float*)d_out;

    void *qp, *kp, *vtp, *kmp, *vmtp, *hx, *hl, *hqw, *hkw, *hvw;
    float *c1p, *c2p;
    cudaGetSymbolAddress(&qp,   g_q);
    cudaGetSymbolAddress(&kp,   g_k);
    cudaGetSymbolAddress(&vtp,  g_vt);
    cudaGetSymbolAddress(&kmp,  g_km);
    cudaGetSymbolAddress(&vmtp, g_vmt);
    cudaGetSymbolAddress(&hx,   g_hx);
    cudaGetSymbolAddress(&hl,   g_hl);
    cudaGetSymbolAddress(&hqw,  g_hqw);
    cudaGetSymbolAddress(&hkw,  g_hkw);
    cudaGetSymbolAddress(&hvw,  g_hvw);
    cudaGetSymbolAddress((void**)&c1p, g_c1);
    cudaGetSymbolAddress((void**)&c2p, g_c2);

    const dim3 tpb(256);
    const int gsmem = 4 * GEMM_STG * (int)sizeof(uint32_t);  // 40960 B

    // 0) fp32 -> fp16 conversions
    const int nq8 = (T_LEN * BB * E_DIM) / 8;           // 524288
    const int nl8 = (2 * M_MEM * BB * E_DIM) / 8;       // 524288
    const int nw8 = (E_DIM * E_DIM) / 8;                // 131072
    CS s0 = { (const float4*)query, (uint4*)hx,  nq8 };
    CS s1 = { (const float4*)lcr,   (uint4*)hl,  nl8 };
    CS s2 = { (const float4*)q_w,   (uint4*)hqw, nw8 };
    CS s3 = { (const float4*)k_w,   (uint4*)hkw, nw8 };
    CS s4 = { (const float4*)v_w,   (uint4*)hvw, nw8 };
    cvt_k<<<dim3(nq8 / 256, 5), tpb>>>(s0, s1, s2, s3, s4);

    // 1) projections (pure fp16 HGEMM)
    const __half* hxp = (const __half*)hx;
    const __half* hlp = (const __half*)hl;
    HGC c0 = { hxp, (const __half*)hqw, q_b, qp,   0.125f, 32, T_LEN, 1 };
    HGC c1 = { hxp, (const __half*)hkw, k_b, kp,   1.f,    32, T_LEN, 1 };
    HGC c2 = { hxp, (const __half*)hvw, v_b, vtp,  1.f,    32, T_LEN, 2 };
    HGC c3 = { hlp,                              (const __half*)hkw, k_b, kmp,  1.f, 16, M_MEM, 1 };
    HGC c4 = { hlp + (size_t)M_MEM * BB * E_DIM, (const __half*)hvw, v_b, vmtp, 1.f, 16, M_MEM, 2 };
    gemm_proj<<<dim3(E_DIM / 128, 32, 5), tpb, gsmem>>>(c0, c1, c2, c3, c4);

    // 2) fused attention
    const int asmem = (2 * 64 * AS + 8 * 16 * AS) * (int)sizeof(uint32_t);  // 36864 B
    attn_fused<<<dim3(T_LEN / 128, H_NUM, 4), tpb, asmem>>>(
        (const __half*)qp, (const __half*)kp, (const __half*)vtp,
        (const __half*)kmp, (const __half*)vmtp, pos, memb, c1p, c2p);

    // 3) output projection (fp32 ctx1+ctx2 fused)
    gemm_out_k<<<dim3(E_DIM / 128, (T_LEN * BB) / 128), tpb, gsmem>>>(
        c1p, c2p, out_w, out_b, out);
}

// round 15
// speedup vs baseline: 3.0682x; 1.1102x over previous
#include <cuda_runtime.h>
#include <cuda_fp16.h>
#include <cstddef>
#include <cstdint>

#define T_LEN 2048
#define BB 2
#define E_DIM 1024
#define H_NUM 16
#define D_HEAD 64
#define M_MEM 1024
#define NEGINF -1e9f

// ---------------- scratch (device globals; allocation-free) ----------------
__device__ __half g_q  [(size_t)BB * H_NUM * T_LEN * D_HEAD];   // [b,h,t,d]
__device__ __half g_k  [(size_t)BB * H_NUM * T_LEN * D_HEAD];   // [b,h,s,d]
__device__ __half g_vt [(size_t)BB * H_NUM * D_HEAD * T_LEN];   // [b,h,d,s]
__device__ __half g_km [(size_t)BB * H_NUM * M_MEM * D_HEAD];   // [b,h,s,d]
__device__ __half g_vmt[(size_t)BB * H_NUM * D_HEAD * M_MEM];   // [b,h,d,s]
__device__ __half g_c1 [(size_t)T_LEN * BB * E_DIM];            // ctx local  (fp16)
__device__ __half g_c2 [(size_t)T_LEN * BB * E_DIM];            // ctx memory (fp16)
// fp16 copies of fp32 inputs (pre-converted once per call)
__device__ __half g_hx [(size_t)T_LEN * BB * E_DIM];            // query
__device__ __half g_hl [(size_t)2 * M_MEM * BB * E_DIM];        // lcr (both)
__device__ __half g_hqw[(size_t)E_DIM * E_DIM];
__device__ __half g_hkw[(size_t)E_DIM * E_DIM];
__device__ __half g_hvw[(size_t)E_DIM * E_DIM];
__device__ __half g_how[(size_t)E_DIM * E_DIM];

// ---------------- fp16 helpers ---------------------------------------------
__device__ __forceinline__ uint32_t f2h2(float a, float b) {
    __half2 h = __floats2half2_rn(a, b);
    return *(uint32_t*)&h;
}

__device__ __forceinline__ uint32_t h2add(uint32_t a, uint32_t b) {
    __half2 r = __hadd2(*(__half2*)&a, *(__half2*)&b);
    return *(uint32_t*)&r;
}

__device__ __forceinline__ void mma_fp16(float* c, const uint32_t* a, const uint32_t* b) {
    asm volatile(
        "mma.sync.aligned.m16n8k16.row.col.f32.f16.f16.f32 "
        "{%0,%1,%2,%3}, {%4,%5,%6,%7}, {%8,%9}, {%0,%1,%2,%3};"
        : "+f"(c[0]), "+f"(c[1]), "+f"(c[2]), "+f"(c[3])
        : "r"(a[0]), "r"(a[1]), "r"(a[2]), "r"(a[3]), "r"(b[0]), "r"(b[1]));
}

// ---------------- fp32 -> fp16 conversion pass -----------------------------
struct CS { const float4* s; uint4* d; int n8; };

__global__ void __launch_bounds__(256)
cvt_k(CS c0, CS c1, CS c2, CS c3, CS c4, CS c5)
{
    CS c = c0;
    const int z = blockIdx.y;
    if (z == 1) c = c1; else if (z == 2) c = c2;
    else if (z == 3) c = c3; else if (z == 4) c = c4;
    else if (z == 5) c = c5;
    const int i = blockIdx.x * 256 + threadIdx.x;
    if (i >= c.n8) return;
    const float4 a = c.s[2 * i];
    const float4 b = c.s[2 * i + 1];
    c.d[i] = make_uint4(f2h2(a.x, a.y), f2h2(a.z, a.w),
                        f2h2(b.x, b.y), f2h2(b.z, b.w));
}

// ---------------- fp16 HGEMM (projections): C = A * W^T + bias -------------
#define GS 20                   // u32 per row (32 halves + pad)
#define GEMM_STG (128 * GS)     // u32 per matrix stage

struct HGC {
    const __half* A; const __half* W; const float* bias; void* out;
    float scale; int ny; int Lrows; int mode;
};

__global__ void __launch_bounds__(256, 2)
gemm_proj(HGC c0, HGC c1, HGC c2, HGC c3, HGC c4)
{
    extern __shared__ uint32_t gsm[];
    HGC c = c0;
    {
        const int z = blockIdx.z;
        if (z == 1) c = c1; else if (z == 2) c = c2;
        else if (z == 3) c = c3; else if (z == 4) c = c4;
    }
    if ((int)blockIdx.y >= c.ny) return;

    uint32_t* Asb = gsm;
    uint32_t* Bsb = gsm + 2 * GEMM_STG;

    const int tid  = threadIdx.x;
    const int warp = tid >> 5;
    const int lane = tid & 31;
    const int g = lane >> 2, t = lane & 3;
    const int wm = warp >> 2;
    const int wn = warp & 3;
    const int row0 = blockIdx.y * 128;
    const int col0 = blockIdx.x * 128;

    const int lr = tid >> 1;           // 0..127
    const int hc = (tid & 1) * 2;      // uint4 offset within row chunk

    float acc[4][4][4];
#pragma unroll
    for (int mt = 0; mt < 4; mt++)
#pragma unroll
        for (int nt = 0; nt < 4; nt++)
#pragma unroll
            for (int i = 0; i < 4; i++) acc[mt][nt][i] = 0.f;

    const uint4* Ap = (const uint4*)(c.A + (size_t)(row0 + lr) * E_DIM) + hc;
    const uint4* Wp = (const uint4*)(c.W + (size_t)(col0 + lr) * E_DIM) + hc;

    uint4 a0 = Ap[0], a1 = Ap[1];
    uint4 w0 = Wp[0], w1 = Wp[1];
    {
        uint4* da = (uint4*)(Asb + lr * GS) + hc;
        uint4* db = (uint4*)(Bsb + lr * GS) + hc;
        da[0] = a0; da[1] = a1;
        db[0] = w0; db[1] = w1;
    }
    __syncthreads();

    for (int kt = 0; kt < E_DIM; kt += 32) {
        const int cur = (kt >> 5) & 1;
        const int nxt = cur ^ 1;
        const bool more = (kt + 32) < E_DIM;
        if (more) {
            const int ku = (kt + 32) >> 3;
            a0 = Ap[ku]; a1 = Ap[ku + 1];
            w0 = Wp[ku]; w1 = Wp[ku + 1];
        }

        const uint32_t* As = Asb + cur * GEMM_STG;
        const uint32_t* Bs = Bsb + cur * GEMM_STG;
#pragma unroll
        for (int ks = 0; ks < 2; ks++) {
            uint32_t af[4][4], bf[4][2];
#pragma unroll
            for (int mt = 0; mt < 4; mt++) {
                const int m = wm * 64 + mt * 16;
                af[mt][0] = As[(m + g    ) * GS + 8*ks + t    ];
                af[mt][1] = As[(m + g + 8) * GS + 8*ks + t    ];
                af[mt][2] = As[(m + g    ) * GS + 8*ks + t + 4];
                af[mt][3] = As[(m + g + 8) * GS + 8*ks + t + 4];
            }
#pragma unroll
            for (int nt = 0; nt < 4; nt++) {
                const int n = wn * 32 + nt * 8;
                bf[nt][0] = Bs[(n + g) * GS + 8*ks + t    ];
                bf[nt][1] = Bs[(n + g) * GS + 8*ks + t + 4];
            }
#pragma unroll
            for (int mt = 0; mt < 4; mt++)
#pragma unroll
                for (int nt = 0; nt < 4; nt++)
                    mma_fp16(acc[mt][nt], af[mt], bf[nt]);
        }

        if (more) {
            uint4* da = (uint4*)(Asb + nxt * GEMM_STG + lr * GS) + hc;
            uint4* db = (uint4*)(Bsb + nxt * GEMM_STG + lr * GS) + hc;
            da[0] = a0; da[1] = a1;
            db[0] = w0; db[1] = w1;
        }
        __syncthreads();
    }

#pragma unroll
    for (int mt = 0; mt < 4; mt++) {
#pragma unroll
        for (int nt = 0; nt < 4; nt++) {
#pragma unroll
            for (int i = 0; i < 2; i++) {
                const int r  = row0 + wm * 64 + mt * 16 + g + i * 8;
                const int c0i = col0 + wn * 32 + nt * 8 + 2 * t;
                const float v0 = (acc[mt][nt][i * 2 + 0] + c.bias[c0i    ]) * c.scale;
                const float v1 = (acc[mt][nt][i * 2 + 1] + c.bias[c0i + 1]) * c.scale;
                const int tt = r >> 1, b = r & 1;
                const int h = c0i >> 6, d = c0i & 63;
                if (c.mode == 1) {
                    ((uint32_t*)c.out)[((((size_t)b * H_NUM + h) * c.Lrows + tt) * 64 + d) >> 1]
                        = f2h2(v0, v1);
                } else {
                    __half* o = (__half*)c.out
                        + (((size_t)b * H_NUM + h) * 64 + d) * c.Lrows + tt;
                    o[0]        = __float2half_rn(v0);
                    o[c.Lrows]  = __float2half_rn(v1);
                }
            }
        }
    }
}

// ---------------- output projection: pure HGEMM, A = ctx1 + ctx2 -----------
__global__ void __launch_bounds__(256, 2)
gemm_out_k(const __half* __restrict__ A1, const __half* __restrict__ A2,
           const __half* __restrict__ W, const float* __restrict__ bias,
           float* __restrict__ out)
{
    extern __shared__ uint32_t gsm[];
    uint32_t* Asb = gsm;
    uint32_t* Bsb = gsm + 2 * GEMM_STG;

    const int tid  = threadIdx.x;
    const int warp = tid >> 5;
    const int lane = tid & 31;
    const int g = lane >> 2, t = lane & 3;
    const int wm = warp >> 2;
    const int wn = warp & 3;
    const int row0 = blockIdx.y * 128;
    const int col0 = blockIdx.x * 128;

    const int lr = tid >> 1;
    const int hc = (tid & 1) * 2;

    float acc[4][4][4];
#pragma unroll
    for (int mt = 0; mt < 4; mt++)
#pragma unroll
        for (int nt = 0; nt < 4; nt++)
#pragma unroll
            for (int i = 0; i < 4; i++) acc[mt][nt][i] = 0.f;

    const uint4* Ap1 = (const uint4*)(A1 + (size_t)(row0 + lr) * E_DIM) + hc;
    const uint4* Ap2 = (const uint4*)(A2 + (size_t)(row0 + lr) * E_DIM) + hc;
    const uint4* Wp  = (const uint4*)(W  + (size_t)(col0 + lr) * E_DIM) + hc;

    uint4 a0 = Ap1[0], a1 = Ap1[1];
    uint4 w0 = Wp[0],  w1 = Wp[1];
    {
        const uint4 b0 = Ap2[0], b1 = Ap2[1];
        a0 = make_uint4(h2add(a0.x, b0.x), h2add(a0.y, b0.y),
                        h2add(a0.z, b0.z), h2add(a0.w, b0.w));
        a1 = make_uint4(h2add(a1.x, b1.x), h2add(a1.y, b1.y),
                        h2add(a1.z, b1.z), h2add(a1.w, b1.w));
        uint4* da = (uint4*)(Asb + lr * GS) + hc;
        uint4* db = (uint4*)(Bsb + lr * GS) + hc;
        da[0] = a0; da[1] = a1;
        db[0] = w0; db[1] = w1;
    }
    __syncthreads();

    for (int kt = 0; kt < E_DIM; kt += 32) {
        const int cur = (kt >> 5) & 1;
        const int nxt = cur ^ 1;
        const bool more = (kt + 32) < E_DIM;
        if (more) {
            const int ku = (kt + 32) >> 3;
            a0 = Ap1[ku]; a1 = Ap1[ku + 1];
            const uint4 b0 = Ap2[ku], b1 = Ap2[ku + 1];
            a0 = make_uint4(h2add(a0.x, b0.x), h2add(a0.y, b0.y),
                            h2add(a0.z, b0.z), h2add(a0.w, b0.w));
            a1 = make_uint4(h2add(a1.x, b1.x), h2add(a1.y, b1.y),
                            h2add(a1.z, b1.z), h2add(a1.w, b1.w));
            w0 = Wp[ku]; w1 = Wp[ku + 1];
        }

        const uint32_t* As = Asb + cur * GEMM_STG;
        const uint32_t* Bs = Bsb + cur * GEMM_STG;
#pragma unroll
        for (int ks = 0; ks < 2; ks++) {
            uint32_t af[4][4], bf[4][2];
#pragma unroll
            for (int mt = 0; mt < 4; mt++) {
                const int m = wm * 64 + mt * 16;
                af[mt][0] = As[(m + g    ) * GS + 8*ks + t    ];
                af[mt][1] = As[(m + g + 8) * GS + 8*ks + t    ];
                af[mt][2] = As[(m + g    ) * GS + 8*ks + t + 4];
                af[mt][3] = As[(m + g + 8) * GS + 8*ks + t + 4];
            }
#pragma unroll
            for (int nt = 0; nt < 4; nt++) {
                const int n = wn * 32 + nt * 8;
                bf[nt][0] = Bs[(n + g) * GS + 8*ks + t    ];
                bf[nt][1] = Bs[(n + g) * GS + 8*ks + t + 4];
            }
#pragma unroll
            for (int mt = 0; mt < 4; mt++)
#pragma unroll
                for (int nt = 0; nt < 4; nt++)
                    mma_fp16(acc[mt][nt], af[mt], bf[nt]);
        }

        if (more) {
            uint4* da = (uint4*)(Asb + nxt * GEMM_STG + lr * GS) + hc;
            uint4* db = (uint4*)(Bsb + nxt * GEMM_STG + lr * GS) + hc;
            da[0] = a0; da[1] = a1;
            db[0] = w0; db[1] = w1;
        }
        __syncthreads();
    }

#pragma unroll
    for (int mt = 0; mt < 4; mt++) {
#pragma unroll
        for (int nt = 0; nt < 4; nt++) {
#pragma unroll
            for (int i = 0; i < 2; i++) {
                const int r  = row0 + wm * 64 + mt * 16 + g + i * 8;
                const int c0 = col0 + wn * 32 + nt * 8 + 2 * t;
                float* o = out + (size_t)r * E_DIM + c0;
                o[0] = acc[mt][nt][i * 2 + 0] + bias[c0];
                o[1] = acc[mt][nt][i * 2 + 1] + bias[c0 + 1];
            }
        }
    }
}

// ---------------- fused attention (fp16 MMA, local + memory) ---------------
#define AS 36

__global__ void __launch_bounds__(256, 1)
attn_fused(const __half* __restrict__ Qg,
           const __half* __restrict__ Kl, const __half* __restrict__ Vtl,
           const __half* __restrict__ Km, const __half* __restrict__ Vtm,
           const float* __restrict__ pos, const float* __restrict__ memb,
           __half* __restrict__ ctx1, __half* __restrict__ ctx2)
{
    extern __shared__ uint32_t smu[];
    uint32_t* Ks = smu;
    uint32_t* Vt = Ks + 64 * AS;
    uint32_t* Ps = Vt + 64 * AS;

    const int z    = blockIdx.z;
    const int kind = z >> 1;
    const int b    = z & 1;
    const bool LOCAL = (kind == 0);
    const __half* Kg  = LOCAL ? Kl  : Km;
    const __half* Vtg = LOCAL ? Vtl : Vtm;
    const int Skeys = LOCAL ? T_LEN : M_MEM;
    __half* ctx = LOCAL ? ctx1 : ctx2;

    const int tid  = threadIdx.x;
    const int warp = tid >> 5;
    const int lane = tid & 31;
    const int g = lane >> 2, t = lane & 3;
    const int h  = blockIdx.y;
    const int t0 = blockIdx.x * 128;
    const int qrow = t0 + warp * 16;
    uint32_t* Pw = Ps + warp * 16 * AS;

    const uint32_t* Qu = (const uint32_t*)Qg
        + ((((size_t)b * H_NUM + h) * T_LEN + qrow) * D_HEAD >> 1);
    uint32_t qf[4][4];
#pragma unroll
    for (int ks = 0; ks < 4; ks++) {
        qf[ks][0] = Qu[(g    ) * 32 + 8*ks + t    ];
        qf[ks][1] = Qu[(g + 8) * 32 + 8*ks + t    ];
        qf[ks][2] = Qu[(g    ) * 32 + 8*ks + t + 4];
        qf[ks][3] = Qu[(g + 8) * 32 + 8*ks + t + 4];
    }

    const int lr_ = tid >> 2;
    const int lq  = (tid & 3) * 2;
    const uint4* KuRow = (const uint4*)(Kg + ((size_t)b * H_NUM + h) * Skeys * D_HEAD)
                         + (size_t)lr_ * 8;
    const uint4* VuRow = (const uint4*)(Vtg + (((size_t)b * H_NUM + h) * D_HEAD + lr_) * Skeys);

    float m0 = -1e30f, m1 = -1e30f;
    float l0 = 0.f, l1 = 0.f;
    float O[8][4];
#pragma unroll
    for (int nt = 0; nt < 8; nt++)
#pragma unroll
        for (int i = 0; i < 4; i++) O[nt][i] = 0.f;

    const int send = LOCAL ? (t0 + 128) : Skeys;

    uint4 ka[2], va[2];
    ka[0] = KuRow[lq];     ka[1] = KuRow[lq + 1];
    va[0] = VuRow[lq];     va[1] = VuRow[lq + 1];

    for (int s0 = 0; s0 < send; s0 += 64) {
        const bool more = (s0 + 64) < send;

        __syncthreads();
        ((uint4*)(Ks + lr_ * AS))[lq]     = ka[0];
        ((uint4*)(Ks + lr_ * AS))[lq + 1] = ka[1];
        ((uint4*)(Vt + lr_ * AS))[lq]     = va[0];
        ((uint4*)(Vt + lr_ * AS))[lq + 1] = va[1];
        __syncthreads();

        if (more) {
            ka[0] = KuRow[(s0 + 64) * 8 + lq];
            ka[1] = KuRow[(s0 + 64) * 8 + lq + 1];
            va[0] = VuRow[(s0 + 64) / 8 + lq];
            va[1] = VuRow[(s0 + 64) / 8 + lq + 1];
        }

        if (LOCAL && s0 > qrow + 15) continue;

        float2 pr0[8], pr1[8];
        if (LOCAL) {
            const size_t pb0 = ((size_t)h * T_LEN + qrow + g    ) * (size_t)T_LEN + s0;
            const size_t pb1 = ((size_t)h * T_LEN + qrow + g + 8) * (size_t)T_LEN + s0;
#pragma unroll
            for (int nt = 0; nt < 8; nt++) {
                pr0[nt] = *(const float2*)(pos + pb0 + nt * 8 + 2 * t);
                pr1[nt] = *(const float2*)(pos + pb1 + nt * 8 + 2 * t);
            }
        }

        float Sa[8][4];
#pragma unroll
        for (int nt = 0; nt < 8; nt++)
#pragma unroll
            for (int i = 0; i < 4; i++) Sa[nt][i] = 0.f;
#pragma unroll
        for (int ks = 0; ks < 4; ks++) {
#pragma unroll
            for (int nt = 0; nt < 8; nt++) {
                uint32_t bf[2];
                bf[0] = Ks[(nt * 8 + g) * AS + 8*ks + t    ];
                bf[1] = Ks[(nt * 8 + g) * AS + 8*ks + t + 4];
                mma_fp16(Sa[nt], qf[ks], bf);
            }
        }

        if (LOCAL) {
            const int r0 = qrow + g, r1 = qrow + g + 8;
#pragma unroll
            for (int nt = 0; nt < 8; nt++) {
                Sa[nt][0] += pr0[nt].x; Sa[nt][1] += pr0[nt].y;
                Sa[nt][2] += pr1[nt].x; Sa[nt][3] += pr1[nt].y;
            }
            if (s0 + 63 > qrow) {
#pragma unroll
                for (int nt = 0; nt < 8; nt++) {
                    const int gc = s0 + nt * 8 + 2 * t;
                    if (gc     > r0) Sa[nt][0] = NEGINF;
                    if (gc + 1 > r0) Sa[nt][1] = NEGINF;
                    if (gc     > r1) Sa[nt][2] = NEGINF;
                    if (gc + 1 > r1) Sa[nt][3] = NEGINF;
                }
            }
        }

        float mn0 = m0, mn1 = m1;
#pragma unroll
        for (int nt = 0; nt < 8; nt++) {
            mn0 = fmaxf(mn0, fmaxf(Sa[nt][0], Sa[nt][1]));
            mn1 = fmaxf(mn1, fmaxf(Sa[nt][2], Sa[nt][3]));
        }
        mn0 = fmaxf(mn0, __shfl_xor_sync(0xffffffffu, mn0, 1));
        mn0 = fmaxf(mn0, __shfl_xor_sync(0xffffffffu, mn0, 2));
        mn1 = fmaxf(mn1, __shfl_xor_sync(0xffffffffu, mn1, 1));
        mn1 = fmaxf(mn1, __shfl_xor_sync(0xffffffffu, mn1, 2));
        const float sc0 = __expf(m0 - mn0);
        const float sc1 = __expf(m1 - mn1);
        m0 = mn0; m1 = mn1;
        float sum0 = 0.f, sum1 = 0.f;
        uint32_t ph[8][2];
#pragma unroll
        for (int nt = 0; nt < 8; nt++) {
            const float p0 = __expf(Sa[nt][0] - m0);
            const float p1 = __expf(Sa[nt][1] - m0);
            const float p2 = __expf(Sa[nt][2] - m1);
            const float p3 = __expf(Sa[nt][3] - m1);
            sum0 += p0 + p1; sum1 += p2 + p3;
            ph[nt][0] = f2h2(p0, p1);
            ph[nt][1] = f2h2(p2, p3);
        }
        l0 = l0 * sc0 + sum0;
        l1 = l1 * sc1 + sum1;

#pragma unroll
        for (int nt = 0; nt < 8; nt++) {
            O[nt][0] *= sc0; O[nt][1] *= sc0;
            O[nt][2] *= sc1; O[nt][3] *= sc1;
        }

        __syncwarp();
#pragma unroll
        for (int nt = 0; nt < 8; nt++) {
            Pw[(g    ) * AS + nt * 4 + t] = ph[nt][0];
            Pw[(g + 8) * AS + nt * 4 + t] = ph[nt][1];
        }
        __syncwarp();

#pragma unroll
        for (int ks = 0; ks < 4; ks++) {
            uint32_t af[4];
            af[0] = Pw[(g    ) * AS + 8*ks + t    ];
            af[1] = Pw[(g + 8) * AS + 8*ks + t    ];
            af[2] = Pw[(g    ) * AS + 8*ks + t + 4];
            af[3] = Pw[(g + 8) * AS + 8*ks + t + 4];
#pragma unroll
            for (int nt = 0; nt < 8; nt++) {
                uint32_t bf[2];
                bf[0] = Vt[(nt * 8 + g) * AS + 8*ks + t    ];
                bf[1] = Vt[(nt * 8 + g) * AS + 8*ks + t + 4];
                mma_fp16(O[nt], af, bf);
            }
        }
    }

    l0 += __shfl_xor_sync(0xffffffffu, l0, 1);
    l0 += __shfl_xor_sync(0xffffffffu, l0, 2);
    l1 += __shfl_xor_sync(0xffffffffu, l1, 1);
    l1 += __shfl_xor_sync(0xffffffffu, l1, 2);

    const float gate = 1.f / (1.f + __expf(-memb[h]));
    const float wgt  = LOCAL ? (1.f - gate) : gate;
    const float li0 = wgt / l0;
    const float li1 = wgt / l1;

    const int r0 = qrow + g, r1 = qrow + g + 8;
#pragma unroll
    for (int nt = 0; nt < 8; nt++) {
        const int c = h * 64 + nt * 8 + 2 * t;
        const size_t i0 = ((size_t)r0 * BB + b) * E_DIM + c;
        const size_t i1 = ((size_t)r1 * BB + b) * E_DIM + c;
        *(uint32_t*)(ctx + i0) = f2h2(O[nt][0] * li0, O[nt][1] * li0);
        *(uint32_t*)(ctx + i1) = f2h2(O[nt][2] * li1, O[nt][3] * li1);
    }
}

// ---------------- launch ---------------------------------------------------
extern "C" void kernel_launch(void* const* d_in, const int* in_sizes, int n_in,
                              void* d_out, int out_size)
{
    const float* query = (const float*)d_in[0];
    const float* pos   = (const float*)d_in[1];
    const float* lcr   = (const float*)d_in[2];
    const float* q_w   = (const float*)d_in[3];
    const float* q_b   = (const float*)d_in[4];
    const float* k_w   = (const float*)d_in[5];
    const float* k_b   = (const float*)d_in[6];
    const float* v_w   = (const float*)d_in[7];
    const float* v_b   = (const float*)d_in[8];
    const float* out_w = (const float*)d_in[9];
    const float* out_b = (const float*)d_in[10];
    const float* memb  = (const float*)d_in[11];
    float* out = (float*)d_out;

    void *qp, *kp, *vtp, *kmp, *vmtp, *hx, *hl, *hqw, *hkw, *hvw, *how, *c1p, *c2p;
    cudaGetSymbolAddress(&qp,   g_q);
    cudaGetSymbolAddress(&kp,   g_k);
    cudaGetSymbolAddress(&vtp,  g_vt);
    cudaGetSymbolAddress(&kmp,  g_km);
    cudaGetSymbolAddress(&vmtp, g_vmt);
    cudaGetSymbolAddress(&hx,   g_hx);
    cudaGetSymbolAddress(&hl,   g_hl);
    cudaGetSymbolAddress(&hqw,  g_hqw);
    cudaGetSymbolAddress(&hkw,  g_hkw);
    cudaGetSymbolAddress(&hvw,  g_hvw);
    cudaGetSymbolAddress(&how,  g_how);
    cudaGetSymbolAddress(&c1p,  g_c1);
    cudaGetSymbolAddress(&c2p,  g_c2);

    const dim3 tpb(256);
    const int gsmem = 4 * GEMM_STG * (int)sizeof(uint32_t);  // 40960 B

    // 0) fp32 -> fp16 conversions (inputs + all four weight matrices)
    const int nq8 = (T_LEN * BB * E_DIM) / 8;           // 524288
    const int nl8 = (2 * M_MEM * BB * E_DIM) / 8;       // 524288
    const int nw8 = (E_DIM * E_DIM) / 8;                // 131072
    CS s0 = { (const float4*)query, (uint4*)hx,  nq8 };
    CS s1 = { (const float4*)lcr,   (uint4*)hl,  nl8 };
    CS s2 = { (const float4*)q_w,   (uint4*)hqw, nw8 };
    CS s3 = { (const float4*)k_w,   (uint4*)hkw, nw8 };
    CS s4 = { (const float4*)v_w,   (uint4*)hvw, nw8 };
    CS s5 = { (const float4*)out_w, (uint4*)how, nw8 };
    cvt_k<<<dim3(nq8 / 256, 6), tpb>>>(s0, s1, s2, s3, s4, s5);

    // 1) projections (pure fp16 HGEMM)
    const __half* hxp = (const __half*)hx;
    const __half* hlp = (const __half*)hl;
    HGC c0 = { hxp, (const __half*)hqw, q_b, qp,   0.125f, 32, T_LEN, 1 };
    HGC c1 = { hxp, (const __half*)hkw, k_b, kp,   1.f,    32, T_LEN, 1 };
    HGC c2 = { hxp, (const __half*)hvw, v_b, vtp,  1.f,    32, T_LEN, 2 };
    HGC c3 = { hlp,                              (const __half*)hkw, k_b, kmp,  1.f, 16, M_MEM, 1 };
    HGC c4 = { hlp + (size_t)M_MEM * BB * E_DIM, (const __half*)hvw, v_b, vmtp, 1.f, 16, M_MEM, 2 };
    gemm_proj<<<dim3(E_DIM / 128, 32, 5), tpb, gsmem>>>(c0, c1, c2, c3, c4);

    // 2) fused attention (writes fp16 ctx)
    const int asmem = (2 * 64 * AS + 8 * 16 * AS) * (int)sizeof(uint32_t);  // 36864 B
    attn_fused<<<dim3(T_LEN / 128, H_NUM, 4), tpb, asmem>>>(
        (const __half*)qp, (const __half*)kp, (const __half*)vtp,
        (const __half*)kmp, (const __half*)vmtp, pos, memb,
        (__half*)c1p, (__half*)c2p);

    // 3) output projection (pure HGEMM, A = ctx1 + ctx2 via HADD2)
    gemm_out_k<<<dim3(E_DIM / 128, (T_LEN * BB) / 128), tpb, gsmem>>>(
        (const __half*)c1p, (const __half*)c2p, (const __half*)how, out_b, out);
}

// round 16
// speedup vs baseline: 3.1515x; 1.0271x over previous
#include <cuda_runtime.h>
#include <cuda_fp16.h>
#include <cstddef>
#include <cstdint>

#define T_LEN 2048
#define BB 2
#define E_DIM 1024
#define H_NUM 16
#define D_HEAD 64
#define M_MEM 1024
#define NEGINF -1e9f

// ---------------- scratch (device globals; allocation-free) ----------------
__device__ __half g_q  [(size_t)BB * H_NUM * T_LEN * D_HEAD];   // [b,h,t,d]
__device__ __half g_k  [(size_t)BB * H_NUM * T_LEN * D_HEAD];   // [b,h,s,d]
__device__ __half g_vt [(size_t)BB * H_NUM * D_HEAD * T_LEN];   // [b,h,d,s]
__device__ __half g_km [(size_t)BB * H_NUM * M_MEM * D_HEAD];   // [b,h,s,d]
__device__ __half g_vmt[(size_t)BB * H_NUM * D_HEAD * M_MEM];   // [b,h,d,s]
__device__ __half g_c1 [(size_t)T_LEN * BB * E_DIM];            // ctx local  (fp16)
__device__ __half g_c2 [(size_t)T_LEN * BB * E_DIM];            // ctx memory (fp16)
// fp16 copies of fp32 inputs (pre-converted once per call)
__device__ __half g_hx [(size_t)T_LEN * BB * E_DIM];            // query
__device__ __half g_hl [(size_t)2 * M_MEM * BB * E_DIM];        // lcr (both)
__device__ __half g_hqw[(size_t)E_DIM * E_DIM];
__device__ __half g_hkw[(size_t)E_DIM * E_DIM];
__device__ __half g_hvw[(size_t)E_DIM * E_DIM];
__device__ __half g_how[(size_t)E_DIM * E_DIM];

// ---------------- fp16 helpers ---------------------------------------------
__device__ __forceinline__ uint32_t f2h2(float a, float b) {
    __half2 h = __floats2half2_rn(a, b);
    return *(uint32_t*)&h;
}

__device__ __forceinline__ uint32_t h2add(uint32_t a, uint32_t b) {
    __half2 r = __hadd2(*(__half2*)&a, *(__half2*)&b);
    return *(uint32_t*)&r;
}

__device__ __forceinline__ void mma_fp16(float* c, const uint32_t* a, const uint32_t* b) {
    asm volatile(
        "mma.sync.aligned.m16n8k16.row.col.f32.f16.f16.f32 "
        "{%0,%1,%2,%3}, {%4,%5,%6,%7}, {%8,%9}, {%0,%1,%2,%3};"
        : "+f"(c[0]), "+f"(c[1]), "+f"(c[2]), "+f"(c[3])
        : "r"(a[0]), "r"(a[1]), "r"(a[2]), "r"(a[3]), "r"(b[0]), "r"(b[1]));
}

// ---------------- fp32 -> fp16 conversion pass -----------------------------
struct CS { const float4* s; uint4* d; int n8; };

__global__ void __launch_bounds__(256)
cvt_k(CS c0, CS c1, CS c2, CS c3, CS c4, CS c5)
{
    CS c = c0;
    const int z = blockIdx.y;
    if (z == 1) c = c1; else if (z == 2) c = c2;
    else if (z == 3) c = c3; else if (z == 4) c = c4;
    else if (z == 5) c = c5;
    const int i = blockIdx.x * 256 + threadIdx.x;
    if (i >= c.n8) return;
    const float4 a = c.s[2 * i];
    const float4 b = c.s[2 * i + 1];
    c.d[i] = make_uint4(f2h2(a.x, a.y), f2h2(a.z, a.w),
                        f2h2(b.x, b.y), f2h2(b.z, b.w));
}

// ---------------- fp16 HGEMM (projections): C = A * W^T + bias -------------
#define GS 20                   // u32 per row (32 halves + pad)
#define GEMM_STG (128 * GS)     // u32 per matrix stage

struct HGC {
    const __half* A; const __half* W; const float* bias; void* out;
    float scale; int ny; int Lrows; int mode;
};

__global__ void __launch_bounds__(256, 2)
gemm_proj(HGC c0, HGC c1, HGC c2, HGC c3, HGC c4)
{
    extern __shared__ uint32_t gsm[];
    HGC c = c0;
    {
        const int z = blockIdx.z;
        if (z == 1) c = c1; else if (z == 2) c = c2;
        else if (z == 3) c = c3; else if (z == 4) c = c4;
    }
    if ((int)blockIdx.y >= c.ny) return;

    uint32_t* Asb = gsm;
    uint32_t* Bsb = gsm + 2 * GEMM_STG;

    const int tid  = threadIdx.x;
    const int warp = tid >> 5;
    const int lane = tid & 31;
    const int g = lane >> 2, t = lane & 3;
    const int wm = warp >> 2;
    const int wn = warp & 3;
    const int row0 = blockIdx.y * 128;
    const int col0 = blockIdx.x * 128;

    const int lr = tid >> 1;           // 0..127
    const int hc = (tid & 1) * 2;      // uint4 offset within row chunk

    float acc[4][4][4];
#pragma unroll
    for (int mt = 0; mt < 4; mt++)
#pragma unroll
        for (int nt = 0; nt < 4; nt++)
#pragma unroll
            for (int i = 0; i < 4; i++) acc[mt][nt][i] = 0.f;

    const uint4* Ap = (const uint4*)(c.A + (size_t)(row0 + lr) * E_DIM) + hc;
    const uint4* Wp = (const uint4*)(c.W + (size_t)(col0 + lr) * E_DIM) + hc;

    uint4 a0 = Ap[0], a1 = Ap[1];
    uint4 w0 = Wp[0], w1 = Wp[1];
    {
        uint4* da = (uint4*)(Asb + lr * GS) + hc;
        uint4* db = (uint4*)(Bsb + lr * GS) + hc;
        da[0] = a0; da[1] = a1;
        db[0] = w0; db[1] = w1;
    }
    __syncthreads();

    for (int kt = 0; kt < E_DIM; kt += 32) {
        const int cur = (kt >> 5) & 1;
        const int nxt = cur ^ 1;
        const bool more = (kt + 32) < E_DIM;
        if (more) {
            const int ku = (kt + 32) >> 3;
            a0 = Ap[ku]; a1 = Ap[ku + 1];
            w0 = Wp[ku]; w1 = Wp[ku + 1];
        }

        const uint32_t* As = Asb + cur * GEMM_STG;
        const uint32_t* Bs = Bsb + cur * GEMM_STG;
#pragma unroll
        for (int ks = 0; ks < 2; ks++) {
            uint32_t af[4][4], bf[4][2];
#pragma unroll
            for (int mt = 0; mt < 4; mt++) {
                const int m = wm * 64 + mt * 16;
                af[mt][0] = As[(m + g    ) * GS + 8*ks + t    ];
                af[mt][1] = As[(m + g + 8) * GS + 8*ks + t    ];
                af[mt][2] = As[(m + g    ) * GS + 8*ks + t + 4];
                af[mt][3] = As[(m + g + 8) * GS + 8*ks + t + 4];
            }
#pragma unroll
            for (int nt = 0; nt < 4; nt++) {
                const int n = wn * 32 + nt * 8;
                bf[nt][0] = Bs[(n + g) * GS + 8*ks + t    ];
                bf[nt][1] = Bs[(n + g) * GS + 8*ks + t + 4];
            }
#pragma unroll
            for (int mt = 0; mt < 4; mt++)
#pragma unroll
                for (int nt = 0; nt < 4; nt++)
                    mma_fp16(acc[mt][nt], af[mt], bf[nt]);
        }

        if (more) {
            uint4* da = (uint4*)(Asb + nxt * GEMM_STG + lr * GS) + hc;
            uint4* db = (uint4*)(Bsb + nxt * GEMM_STG + lr * GS) + hc;
            da[0] = a0; da[1] = a1;
            db[0] = w0; db[1] = w1;
        }
        __syncthreads();
    }

#pragma unroll
    for (int mt = 0; mt < 4; mt++) {
#pragma unroll
        for (int nt = 0; nt < 4; nt++) {
#pragma unroll
            for (int i = 0; i < 2; i++) {
                const int r  = row0 + wm * 64 + mt * 16 + g + i * 8;
                const int c0i = col0 + wn * 32 + nt * 8 + 2 * t;
                const float v0 = (acc[mt][nt][i * 2 + 0] + c.bias[c0i    ]) * c.scale;
                const float v1 = (acc[mt][nt][i * 2 + 1] + c.bias[c0i + 1]) * c.scale;
                const int tt = r >> 1, b = r & 1;
                const int h = c0i >> 6, d = c0i & 63;
                if (c.mode == 1) {
                    ((uint32_t*)c.out)[((((size_t)b * H_NUM + h) * c.Lrows + tt) * 64 + d) >> 1]
                        = f2h2(v0, v1);
                } else {
                    __half* o = (__half*)c.out
                        + (((size_t)b * H_NUM + h) * 64 + d) * c.Lrows + tt;
                    o[0]        = __float2half_rn(v0);
                    o[c.Lrows]  = __float2half_rn(v1);
                }
            }
        }
    }
}

// ---------------- output projection: pure HGEMM, A = ctx1 + ctx2 -----------
__global__ void __launch_bounds__(256, 2)
gemm_out_k(const __half* __restrict__ A1, const __half* __restrict__ A2,
           const __half* __restrict__ W, const float* __restrict__ bias,
           float* __restrict__ out)
{
    extern __shared__ uint32_t gsm[];
    uint32_t* Asb = gsm;
    uint32_t* Bsb = gsm + 2 * GEMM_STG;

    const int tid  = threadIdx.x;
    const int warp = tid >> 5;
    const int lane = tid & 31;
    const int g = lane >> 2, t = lane & 3;
    const int wm = warp >> 2;
    const int wn = warp & 3;
    const int row0 = blockIdx.y * 128;
    const int col0 = blockIdx.x * 128;

    const int lr = tid >> 1;
    const int hc = (tid & 1) * 2;

    float acc[4][4][4];
#pragma unroll
    for (int mt = 0; mt < 4; mt++)
#pragma unroll
        for (int nt = 0; nt < 4; nt++)
#pragma unroll
            for (int i = 0; i < 4; i++) acc[mt][nt][i] = 0.f;

    const uint4* Ap1 = (const uint4*)(A1 + (size_t)(row0 + lr) * E_DIM) + hc;
    const uint4* Ap2 = (const uint4*)(A2 + (size_t)(row0 + lr) * E_DIM) + hc;
    const uint4* Wp  = (const uint4*)(W  + (size_t)(col0 + lr) * E_DIM) + hc;

    uint4 a0 = Ap1[0], a1 = Ap1[1];
    uint4 w0 = Wp[0],  w1 = Wp[1];
    {
        const uint4 b0 = Ap2[0], b1 = Ap2[1];
        a0 = make_uint4(h2add(a0.x, b0.x), h2add(a0.y, b0.y),
                        h2add(a0.z, b0.z), h2add(a0.w, b0.w));
        a1 = make_uint4(h2add(a1.x, b1.x), h2add(a1.y, b1.y),
                        h2add(a1.z, b1.z), h2add(a1.w, b1.w));
        uint4* da = (uint4*)(Asb + lr * GS) + hc;
        uint4* db = (uint4*)(Bsb + lr * GS) + hc;
        da[0] = a0; da[1] = a1;
        db[0] = w0; db[1] = w1;
    }
    __syncthreads();

    for (int kt = 0; kt < E_DIM; kt += 32) {
        const int cur = (kt >> 5) & 1;
        const int nxt = cur ^ 1;
        const bool more = (kt + 32) < E_DIM;
        if (more) {
            const int ku = (kt + 32) >> 3;
            a0 = Ap1[ku]; a1 = Ap1[ku + 1];
            const uint4 b0 = Ap2[ku], b1 = Ap2[ku + 1];
            a0 = make_uint4(h2add(a0.x, b0.x), h2add(a0.y, b0.y),
                            h2add(a0.z, b0.z), h2add(a0.w, b0.w));
            a1 = make_uint4(h2add(a1.x, b1.x), h2add(a1.y, b1.y),
                            h2add(a1.z, b1.z), h2add(a1.w, b1.w));
            w0 = Wp[ku]; w1 = Wp[ku + 1];
        }

        const uint32_t* As = Asb + cur * GEMM_STG;
        const uint32_t* Bs = Bsb + cur * GEMM_STG;
#pragma unroll
        for (int ks = 0; ks < 2; ks++) {
            uint32_t af[4][4], bf[4][2];
#pragma unroll
            for (int mt = 0; mt < 4; mt++) {
                const int m = wm * 64 + mt * 16;
                af[mt][0] = As[(m + g    ) * GS + 8*ks + t    ];
                af[mt][1] = As[(m + g + 8) * GS + 8*ks + t    ];
                af[mt][2] = As[(m + g    ) * GS + 8*ks + t + 4];
                af[mt][3] = As[(m + g + 8) * GS + 8*ks + t + 4];
            }
#pragma unroll
            for (int nt = 0; nt < 4; nt++) {
                const int n = wn * 32 + nt * 8;
                bf[nt][0] = Bs[(n + g) * GS + 8*ks + t    ];
                bf[nt][1] = Bs[(n + g) * GS + 8*ks + t + 4];
            }
#pragma unroll
            for (int mt = 0; mt < 4; mt++)
#pragma unroll
                for (int nt = 0; nt < 4; nt++)
                    mma_fp16(acc[mt][nt], af[mt], bf[nt]);
        }

        if (more) {
            uint4* da = (uint4*)(Asb + nxt * GEMM_STG + lr * GS) + hc;
            uint4* db = (uint4*)(Bsb + nxt * GEMM_STG + lr * GS) + hc;
            da[0] = a0; da[1] = a1;
            db[0] = w0; db[1] = w1;
        }
        __syncthreads();
    }

#pragma unroll
    for (int mt = 0; mt < 4; mt++) {
#pragma unroll
        for (int nt = 0; nt < 4; nt++) {
#pragma unroll
            for (int i = 0; i < 2; i++) {
                const int r  = row0 + wm * 64 + mt * 16 + g + i * 8;
                const int c0 = col0 + wn * 32 + nt * 8 + 2 * t;
                float* o = out + (size_t)r * E_DIM + c0;
                o[0] = acc[mt][nt][i * 2 + 0] + bias[c0];
                o[1] = acc[mt][nt][i * 2 + 1] + bias[c0 + 1];
            }
        }
    }
}

// ---------------- fused attention (fp16 MMA, 2 CTAs/SM) --------------------
#define AS 36

__global__ void __launch_bounds__(256, 2)
attn_fused(const __half* __restrict__ Qg,
           const __half* __restrict__ Kl, const __half* __restrict__ Vtl,
           const __half* __restrict__ Km, const __half* __restrict__ Vtm,
           const float* __restrict__ pos, const float* __restrict__ memb,
           __half* __restrict__ ctx1, __half* __restrict__ ctx2)
{
    extern __shared__ uint32_t smu[];
    uint32_t* Ks = smu;
    uint32_t* Vt = Ks + 64 * AS;
    uint32_t* Ps = Vt + 64 * AS;

    const int z    = blockIdx.z;
    const int kind = z >> 1;
    const int b    = z & 1;
    const bool LOCAL = (kind == 0);
    const __half* Kg  = LOCAL ? Kl  : Km;
    const __half* Vtg = LOCAL ? Vtl : Vtm;
    const int Skeys = LOCAL ? T_LEN : M_MEM;
    __half* ctx = LOCAL ? ctx1 : ctx2;

    const int tid  = threadIdx.x;
    const int warp = tid >> 5;
    const int lane = tid & 31;
    const int g = lane >> 2, t = lane & 3;
    const int h  = blockIdx.y;
    const int t0 = blockIdx.x * 128;
    const int qrow = t0 + warp * 16;
    uint32_t* Pw = Ps + warp * 16 * AS;

    const uint32_t* Qu = (const uint32_t*)Qg
        + ((((size_t)b * H_NUM + h) * T_LEN + qrow) * D_HEAD >> 1);
    uint32_t qf[4][4];
#pragma unroll
    for (int ks = 0; ks < 4; ks++) {
        qf[ks][0] = Qu[(g    ) * 32 + 8*ks + t    ];
        qf[ks][1] = Qu[(g + 8) * 32 + 8*ks + t    ];
        qf[ks][2] = Qu[(g    ) * 32 + 8*ks + t + 4];
        qf[ks][3] = Qu[(g + 8) * 32 + 8*ks + t + 4];
    }

    const int lr_ = tid >> 2;
    const int lq  = (tid & 3) * 2;
    const uint4* KuRow = (const uint4*)(Kg + ((size_t)b * H_NUM + h) * Skeys * D_HEAD)
                         + (size_t)lr_ * 8;
    const uint4* VuRow = (const uint4*)(Vtg + (((size_t)b * H_NUM + h) * D_HEAD + lr_) * Skeys);

    float m0 = -1e30f, m1 = -1e30f;
    float l0 = 0.f, l1 = 0.f;
    float O[8][4];
#pragma unroll
    for (int nt = 0; nt < 8; nt++)
#pragma unroll
        for (int i = 0; i < 4; i++) O[nt][i] = 0.f;

    const int send = LOCAL ? (t0 + 128) : Skeys;

    uint4 ka[2], va[2];
    ka[0] = KuRow[lq];     ka[1] = KuRow[lq + 1];
    va[0] = VuRow[lq];     va[1] = VuRow[lq + 1];

    for (int s0 = 0; s0 < send; s0 += 64) {
        const bool more = (s0 + 64) < send;

        __syncthreads();
        ((uint4*)(Ks + lr_ * AS))[lq]     = ka[0];
        ((uint4*)(Ks + lr_ * AS))[lq + 1] = ka[1];
        ((uint4*)(Vt + lr_ * AS))[lq]     = va[0];
        ((uint4*)(Vt + lr_ * AS))[lq + 1] = va[1];
        __syncthreads();

        if (more) {
            ka[0] = KuRow[(s0 + 64) * 8 + lq];
            ka[1] = KuRow[(s0 + 64) * 8 + lq + 1];
            va[0] = VuRow[(s0 + 64) / 8 + lq];
            va[1] = VuRow[(s0 + 64) / 8 + lq + 1];
        }

        if (LOCAL && s0 > qrow + 15) continue;

        float Sa[8][4];
#pragma unroll
        for (int nt = 0; nt < 8; nt++)
#pragma unroll
            for (int i = 0; i < 4; i++) Sa[nt][i] = 0.f;
#pragma unroll
        for (int ks = 0; ks < 4; ks++) {
#pragma unroll
            for (int nt = 0; nt < 8; nt++) {
                uint32_t bf[2];
                bf[0] = Ks[(nt * 8 + g) * AS + 8*ks + t    ];
                bf[1] = Ks[(nt * 8 + g) * AS + 8*ks + t + 4];
                mma_fp16(Sa[nt], qf[ks], bf);
            }
        }

        if (LOCAL) {
            const int r0 = qrow + g, r1 = qrow + g + 8;
            const size_t pb0 = ((size_t)h * T_LEN + r0) * (size_t)T_LEN + s0;
            const size_t pb1 = ((size_t)h * T_LEN + r1) * (size_t)T_LEN + s0;
#pragma unroll
            for (int nt = 0; nt < 8; nt++) {
                const float2 p0 = *(const float2*)(pos + pb0 + nt * 8 + 2 * t);
                const float2 p1 = *(const float2*)(pos + pb1 + nt * 8 + 2 * t);
                Sa[nt][0] += p0.x; Sa[nt][1] += p0.y;
                Sa[nt][2] += p1.x; Sa[nt][3] += p1.y;
            }
            if (s0 + 63 > qrow) {
#pragma unroll
                for (int nt = 0; nt < 8; nt++) {
                    const int gc = s0 + nt * 8 + 2 * t;
                    if (gc     > r0) Sa[nt][0] = NEGINF;
                    if (gc + 1 > r0) Sa[nt][1] = NEGINF;
                    if (gc     > r1) Sa[nt][2] = NEGINF;
                    if (gc + 1 > r1) Sa[nt][3] = NEGINF;
                }
            }
        }

        float mn0 = m0, mn1 = m1;
#pragma unroll
        for (int nt = 0; nt < 8; nt++) {
            mn0 = fmaxf(mn0, fmaxf(Sa[nt][0], Sa[nt][1]));
            mn1 = fmaxf(mn1, fmaxf(Sa[nt][2], Sa[nt][3]));
        }
        mn0 = fmaxf(mn0, __shfl_xor_sync(0xffffffffu, mn0, 1));
        mn0 = fmaxf(mn0, __shfl_xor_sync(0xffffffffu, mn0, 2));
        mn1 = fmaxf(mn1, __shfl_xor_sync(0xffffffffu, mn1, 1));
        mn1 = fmaxf(mn1, __shfl_xor_sync(0xffffffffu, mn1, 2));
        const float sc0 = __expf(m0 - mn0);
        const float sc1 = __expf(m1 - mn1);
        m0 = mn0; m1 = mn1;
        float sum0 = 0.f, sum1 = 0.f;
        uint32_t ph[8][2];
#pragma unroll
        for (int nt = 0; nt < 8; nt++) {
            const float p0 = __expf(Sa[nt][0] - m0);
            const float p1 = __expf(Sa[nt][1] - m0);
            const float p2 = __expf(Sa[nt][2] - m1);
            const float p3 = __expf(Sa[nt][3] - m1);
            sum0 += p0 + p1; sum1 += p2 + p3;
            ph[nt][0] = f2h2(p0, p1);
            ph[nt][1] = f2h2(p2, p3);
        }
        l0 = l0 * sc0 + sum0;
        l1 = l1 * sc1 + sum1;

#pragma unroll
        for (int nt = 0; nt < 8; nt++) {
            O[nt][0] *= sc0; O[nt][1] *= sc0;
            O[nt][2] *= sc1; O[nt][3] *= sc1;
        }

        __syncwarp();
#pragma unroll
        for (int nt = 0; nt < 8; nt++) {
            Pw[(g    ) * AS + nt * 4 + t] = ph[nt][0];
            Pw[(g + 8) * AS + nt * 4 + t] = ph[nt][1];
        }
        __syncwarp();

#pragma unroll
        for (int ks = 0; ks < 4; ks++) {
            uint32_t af[4];
            af[0] = Pw[(g    ) * AS + 8*ks + t    ];
            af[1] = Pw[(g + 8) * AS + 8*ks + t    ];
            af[2] = Pw[(g    ) * AS + 8*ks + t + 4];
            af[3] = Pw[(g + 8) * AS + 8*ks + t + 4];
#pragma unroll
            for (int nt = 0; nt < 8; nt++) {
                uint32_t bf[2];
                bf[0] = Vt[(nt * 8 + g) * AS + 8*ks + t    ];
                bf[1] = Vt[(nt * 8 + g) * AS + 8*ks + t + 4];
                mma_fp16(O[nt], af, bf);
            }
        }
    }

    l0 += __shfl_xor_sync(0xffffffffu, l0, 1);
    l0 += __shfl_xor_sync(0xffffffffu, l0, 2);
    l1 += __shfl_xor_sync(0xffffffffu, l1, 1);
    l1 += __shfl_xor_sync(0xffffffffu, l1, 2);

    const float gate = 1.f / (1.f + __expf(-memb[h]));
    const float wgt  = LOCAL ? (1.f - gate) : gate;
    const float li0 = wgt / l0;
    const float li1 = wgt / l1;

    const int r0 = qrow + g, r1 = qrow + g + 8;
#pragma unroll
    for (int nt = 0; nt < 8; nt++) {
        const int c = h * 64 + nt * 8 + 2 * t;
        const size_t i0 = ((size_t)r0 * BB + b) * E_DIM + c;
        const size_t i1 = ((size_t)r1 * BB + b) * E_DIM + c;
        *(uint32_t*)(ctx + i0) = f2h2(O[nt][0] * li0, O[nt][1] * li0);
        *(uint32_t*)(ctx + i1) = f2h2(O[nt][2] * li1, O[nt][3] * li1);
    }
}

// ---------------- launch ---------------------------------------------------
extern "C" void kernel_launch(void* const* d_in, const int* in_sizes, int n_in,
                              void* d_out, int out_size)
{
    const float* query = (const float*)d_in[0];
    const float* pos   = (const float*)d_in[1];
    const float* lcr   = (const float*)d_in[2];
    const float* q_w   = (const float*)d_in[3];
    const float* q_b   = (const float*)d_in[4];
    const float* k_w   = (const float*)d_in[5];
    const float* k_b   = (const float*)d_in[6];
    const float* v_w   = (const float*)d_in[7];
    const float* v_b   = (const float*)d_in[8];
    const float* out_w = (const float*)d_in[9];
    const float* out_b = (const float*)d_in[10];
    const float* memb  = (const float*)d_in[11];
    float* out = (float*)d_out;

    void *qp, *kp, *vtp, *kmp, *vmtp, *hx, *hl, *hqw, *hkw, *hvw, *how, *c1p, *c2p;
    cudaGetSymbolAddress(&qp,   g_q);
    cudaGetSymbolAddress(&kp,   g_k);
    cudaGetSymbolAddress(&vtp,  g_vt);
    cudaGetSymbolAddress(&kmp,  g_km);
    cudaGetSymbolAddress(&vmtp, g_vmt);
    cudaGetSymbolAddress(&hx,   g_hx);
    cudaGetSymbolAddress(&hl,   g_hl);
    cudaGetSymbolAddress(&hqw,  g_hqw);
    cudaGetSymbolAddress(&hkw,  g_hkw);
    cudaGetSymbolAddress(&hvw,  g_hvw);
    cudaGetSymbolAddress(&how,  g_how);
    cudaGetSymbolAddress(&c1p,  g_c1);
    cudaGetSymbolAddress(&c2p,  g_c2);

    const dim3 tpb(256);
    const int gsmem = 4 * GEMM_STG * (int)sizeof(uint32_t);  // 40960 B

    // 0) fp32 -> fp16 conversions (inputs + all four weight matrices)
    const int nq8 = (T_LEN * BB * E_DIM) / 8;           // 524288
    const int nl8 = (2 * M_MEM * BB * E_DIM) / 8;       // 524288
    const int nw8 = (E_DIM * E_DIM) / 8;                // 131072
    CS s0 = { (const float4*)query, (uint4*)hx,  nq8 };
    CS s1 = { (const float4*)lcr,   (uint4*)hl,  nl8 };
    CS s2 = { (const float4*)q_w,   (uint4*)hqw, nw8 };
    CS s3 = { (const float4*)k_w,   (uint4*)hkw, nw8 };
    CS s4 = { (const float4*)v_w,   (uint4*)hvw, nw8 };
    CS s5 = { (const float4*)out_w, (uint4*)how, nw8 };
    cvt_k<<<dim3(nq8 / 256, 6), tpb>>>(s0, s1, s2, s3, s4, s5);

    // 1) projections (pure fp16 HGEMM)
    const __half* hxp = (const __half*)hx;
    const __half* hlp = (const __half*)hl;
    HGC c0 = { hxp, (const __half*)hqw, q_b, qp,   0.125f, 32, T_LEN, 1 };
    HGC c1 = { hxp, (const __half*)hkw, k_b, kp,   1.f,    32, T_LEN, 1 };
    HGC c2 = { hxp, (const __half*)hvw, v_b, vtp,  1.f,    32, T_LEN, 2 };
    HGC c3 = { hlp,                              (const __half*)hkw, k_b, kmp,  1.f, 16, M_MEM, 1 };
    HGC c4 = { hlp + (size_t)M_MEM * BB * E_DIM, (const __half*)hvw, v_b, vmtp, 1.f, 16, M_MEM, 2 };
    gemm_proj<<<dim3(E_DIM / 128, 32, 5), tpb, gsmem>>>(c0, c1, c2, c3, c4);

    // 2) fused attention (2 CTAs/SM, writes fp16 ctx)
    const int asmem = (2 * 64 * AS + 8 * 16 * AS) * (int)sizeof(uint32_t);  // 36864 B
    attn_fused<<<dim3(T_LEN / 128, H_NUM, 4), tpb, asmem>>>(
        (const __half*)qp, (const __half*)kp, (const __half*)vtp,
        (const __half*)kmp, (const __half*)vmtp, pos, memb,
        (__half*)c1p, (__half*)c2p);

    // 3) output projection (pure HGEMM, A = ctx1 + ctx2 via HADD2)
    gemm_out_k<<<dim3(E_DIM / 128, (T_LEN * BB) / 128), tpb, gsmem>>>(
        (const __half*)c1p, (const __half*)c2p, (const __half*)how, out_b, out);
}